// round 11
// baseline (speedup 1.0000x reference)
#include <cuda_runtime.h>
#include <cuda_fp16.h>
#include <cstdint>

// Decoder: out[b,d] = (x[b,d] - diag_t[b,d]) * exp(-diag_s[b,d])
// R10: R9 (two 8-warp groups, s-MLP/t-MLP) + instruction-level interleave of
// B-LDG / A-LDSM into the volatile HMMA stream so L1TEX and tensor overlap.

namespace {

constexpr int Hn = 512;
constexpr int LDA = 520;        // A stride in halves (1040 B)
constexpr int NTHREADS = 512;   // 2 groups x 8 warps (2M x 4N per half)

// blob (u32 = f16x2), fragment-major in 16-k chunks: mlp0 L1,L2,L3 then mlp1
__device__ __align__(16) uint32_t g_wblob[557056];
__constant__ int c_blob_off[7] = {0, 16384, 147456, 278528, 294912, 425984, 557056};

// per-group smem layout (bytes)
constexpr int OFF_STG  = 66560;    // 64 x 264 halves staging (33792 B)
constexpr int OFF_BIAS = 100352;   // 3 x 512 f32 (6144 B)
constexpr int OFF_RED  = 106496;   // 4 x 64 f32 (1024 B)
constexpr int OFF_S    = 107520;   // 64 f32 (256 B)
constexpr int GRP      = 107776;
constexpr int SMEM_BYTES = 2 * GRP;   // 215552

__device__ __forceinline__ void mma16(float c[4], const unsigned a[4],
                                      unsigned b0, unsigned b1) {
    asm volatile(
        "mma.sync.aligned.m16n8k16.row.col.f32.f16.f16.f32 "
        "{%0,%1,%2,%3}, {%4,%5,%6,%7}, {%8,%9}, {%0,%1,%2,%3};"
        : "+f"(c[0]), "+f"(c[1]), "+f"(c[2]), "+f"(c[3])
        : "r"(a[0]), "r"(a[1]), "r"(a[2]), "r"(a[3]), "r"(b0), "r"(b1));
}
__device__ __forceinline__ void ldsm4(unsigned r[4], uint32_t addr) {
    asm volatile("ldmatrix.sync.aligned.m8n8.x4.shared.b16 {%0,%1,%2,%3}, [%4];"
                 : "=r"(r[0]), "=r"(r[1]), "=r"(r[2]), "=r"(r[3]) : "r"(addr));
}
__device__ __forceinline__ void ldg128(uint4& v, const uint4* p) {
    asm volatile("ld.global.nc.v4.u32 {%0,%1,%2,%3}, [%4];"
                 : "=r"(v.x), "=r"(v.y), "=r"(v.z), "=r"(v.w) : "l"(p));
}
__device__ __forceinline__ void gbar(int id) {
    asm volatile("bar.sync %0, 256;" :: "r"(id) : "memory");
}
__device__ __forceinline__ float fast_tanh(float x) {
    float e = __expf(2.0f * x);
    return 1.0f - __fdividef(2.0f, e + 1.0f);
}
__device__ __forceinline__ uint32_t pack_f16x2(float lo, float hi) {
    uint32_t r;
    asm("cvt.rn.f16x2.f32 %0, %1, %2;" : "=r"(r) : "f"(hi), "f"(lo));
    return r;
}

// ---- fused prep: all 6 hidden-layer weights -> fp16 fragment blob ----
__global__ void prep_kernel(const float* __restrict__ W0, const float* __restrict__ W1,
                            const float* __restrict__ W2, const float* __restrict__ W3,
                            const float* __restrict__ W4, const float* __restrict__ W5) {
    const int eg = blockIdx.x * blockDim.x + threadIdx.x;
    if (eg >= 557056) return;
    const float* srcs[6] = {W0, W1, W2, W3, W4, W5};
    int slot = 0;
    while (eg >= c_blob_off[slot + 1]) ++slot;
    const float* W = srcs[slot];
    const int e = eg - c_blob_off[slot];
    const int q = e & 3;
    const int lane = (e >> 2) & 31;
    const int p = (e >> 7) & 3;
    const int wn = (e >> 9) & 7;
    const int chunk = e >> 12;
    const int k = chunk * 16 + 2 * (lane & 3) + 8 * (q & 1);
    const int col = wn * 64 + (2 * p + (q >> 1)) * 8 + (lane >> 2);
    g_wblob[eg] = pack_f16x2(W[k * Hn + col], W[(k + 1) * Hn + col]);
}

// ---- main ----
__device__ __forceinline__ void do_mma(float acc[2][8][4], const unsigned a[2][4],
                                       const uint4 b[4]) {
#pragma unroll
    for (int p = 0; p < 4; ++p) {
        mma16(acc[0][2 * p],     a[0], b[p].x, b[p].y);
        mma16(acc[1][2 * p],     a[1], b[p].x, b[p].y);
        mma16(acc[0][2 * p + 1], a[0], b[p].z, b[p].w);
        mma16(acc[1][2 * p + 1], a[1], b[p].z, b[p].w);
    }
}
// 16 HMMA on (a,b) with prefetch for step kh+2 interleaved into the stream.
// b[p] is refilled immediately after its last consuming HMMA; a after all 16.
__device__ __forceinline__ void fused_step(float acc[2][8][4], unsigned a[2][4],
                                           uint4 b[4], uint32_t na0, uint32_t na1,
                                           const uint4* __restrict__ nbp) {
#pragma unroll
    for (int p = 0; p < 4; ++p) {
        mma16(acc[0][2 * p],     a[0], b[p].x, b[p].y);
        mma16(acc[1][2 * p],     a[1], b[p].x, b[p].y);
        mma16(acc[0][2 * p + 1], a[0], b[p].z, b[p].w);
        mma16(acc[1][2 * p + 1], a[1], b[p].z, b[p].w);
        ldg128(b[p], nbp + p * 32);
    }
    ldsm4(a[0], na0);
    ldsm4(a[1], na1);
}
__device__ __forceinline__ void load_b(uint4 b[4], const uint4* __restrict__ bp) {
#pragma unroll
    for (int p = 0; p < 4; ++p) ldg128(b[p], bp + p * 32);
}
__device__ __forceinline__ void load_a(unsigned a[2][4], uint32_t a0, uint32_t a1) {
    ldsm4(a[0], a0);
    ldsm4(a[1], a1);
}

// one 256-col half of a layer; KH = K/16
template <int KH>
__device__ __forceinline__ void gemm_half(const uint4* __restrict__ Wg, int h,
                                          const __half* sA, float acc[2][8][4],
                                          int lane, int wm, int wnl) {
#pragma unroll
    for (int m = 0; m < 2; ++m)
#pragma unroll
        for (int n = 0; n < 8; ++n)
#pragma unroll
            for (int q = 0; q < 4; ++q) acc[m][n][q] = 0.0f;

    const uint4* bp = Wg + (h * 4 + wnl) * 128 + lane;
    const int arow = wm * 32 + (lane & 15);
    const int acol = (lane >> 4) * 8;
    uint32_t a0 = (unsigned)__cvta_generic_to_shared(sA + arow * LDA + acol);
    uint32_t a1 = a0 + 16 * LDA * 2;

    unsigned a[2][2][4];
    uint4 b[2][4];
    load_a(a[0], a0, a1);
    load_b(b[0], bp);
    load_a(a[1], a0 + 32, a1 + 32);
    load_b(b[1], bp + 1024);

#pragma unroll 2
    for (int kh = 0; kh < KH - 2; ++kh) {
        const int s = kh & 1;
        fused_step(acc, a[s], b[s], a0 + (kh + 2) * 32, a1 + (kh + 2) * 32,
                   bp + (size_t)(kh + 2) * 1024);
    }
    do_mma(acc, a[(KH - 2) & 1], b[(KH - 2) & 1]);
    do_mma(acc, a[(KH - 1) & 1], b[(KH - 1) & 1]);
}

// tanh(acc+bias) for half 0 -> staging (stride 264 halves)
__device__ __forceinline__ void store_stg(const float acc[2][8][4], char* stg,
                                          const float* lb, int lane, int wm, int wnl) {
    const int g8 = lane >> 2, t4 = lane & 3;
#pragma unroll
    for (int m = 0; m < 2; ++m) {
        const int row0 = wm * 32 + m * 16 + g8;
#pragma unroll
        for (int n = 0; n < 8; ++n) {
            const int col = wnl * 64 + n * 8 + 2 * t4;
            const float b0 = lb[col], b1 = lb[col + 1];
            *(uint32_t*)(stg + (row0 * 264 + col) * 2) =
                pack_f16x2(fast_tanh(acc[m][n][0] + b0), fast_tanh(acc[m][n][1] + b1));
            *(uint32_t*)(stg + ((row0 + 8) * 264 + col) * 2) =
                pack_f16x2(fast_tanh(acc[m][n][2] + b0), fast_tanh(acc[m][n][3] + b1));
        }
    }
}
// tanh(acc+bias) for half 1 -> sA cols 256..511
__device__ __forceinline__ void store_hi(const float acc[2][8][4], __half* sA,
                                         const float* lb, int lane, int wm, int wnl) {
    const int g8 = lane >> 2, t4 = lane & 3;
#pragma unroll
    for (int m = 0; m < 2; ++m) {
        const int row0 = wm * 32 + m * 16 + g8;
#pragma unroll
        for (int n = 0; n < 8; ++n) {
            const int col = 256 + wnl * 64 + n * 8 + 2 * t4;
            const float b0 = lb[col], b1 = lb[col + 1];
            *(uint32_t*)(sA + row0 * LDA + col) =
                pack_f16x2(fast_tanh(acc[m][n][0] + b0), fast_tanh(acc[m][n][1] + b1));
            *(uint32_t*)(sA + (row0 + 8) * LDA + col) =
                pack_f16x2(fast_tanh(acc[m][n][2] + b0), fast_tanh(acc[m][n][3] + b1));
        }
    }
}

template <int KH>
__device__ __forceinline__ void process_layer(const uint4* __restrict__ Wg,
                                              const float* lb, __half* sA, char* stg,
                                              float acc[2][8][4], int lane, int wm,
                                              int wnl, int gtid, int barid) {
    gemm_half<KH>(Wg, 0, sA, acc, lane, wm, wnl);
    store_stg(acc, stg, lb, lane, wm, wnl);
    gemm_half<KH>(Wg, 1, sA, acc, lane, wm, wnl);
    gbar(barid);   // all A reads done; stg writes visible
    store_hi(acc, sA, lb, lane, wm, wnl);
#pragma unroll
    for (int j = 0; j < 8; ++j) {   // copy stg -> sA cols 0..255
        const int f4 = gtid + j * 256;
        const int row = f4 >> 5, c = f4 & 31;
        *(uint4*)((char*)sA + row * 1040 + c * 16) =
            *(const uint4*)(stg + row * 528 + c * 16);
    }
    gbar(barid);   // sA ready for next layer
}

__global__ __launch_bounds__(NTHREADS, 1)
void decoder_kernel(const float* __restrict__ x, const float* __restrict__ koop,
                    const float* __restrict__ sb1, const float* __restrict__ sb2,
                    const float* __restrict__ sb3,
                    const float* __restrict__ sW4, const float* __restrict__ sb4,
                    const float* __restrict__ tb1, const float* __restrict__ tb2,
                    const float* __restrict__ tb3,
                    const float* __restrict__ tW4, const float* __restrict__ tb4,
                    float* __restrict__ out) {
    extern __shared__ char smem[];
    const int tid = threadIdx.x, lane = tid & 31, wid = tid >> 5;
    const int grp = wid >> 3, gwid = wid & 7, gtid = tid & 255;
    const int wm = gwid >> 2, wnl = gwid & 3;
    const int barid = 1 + grp;
    char* gb = smem + grp * GRP;
    __half* sA = (__half*)gb;
    char* stg = gb + OFF_STG;
    float* sBias = (float*)(gb + OFF_BIAS);
    float* sRed = (float*)(gb + OFF_RED);
    float* sSg = (float*)(gb + OFF_S);
    const int b = blockIdx.x;

    const float* bias1 = grp ? tb1 : sb1;
    const float* bias2 = grp ? tb2 : sb2;
    const float* bias3 = grp ? tb3 : sb3;
    const float* W4 = grp ? tW4 : sW4;
    const float* b4 = grp ? tb4 : sb4;
    const uint4* W1 = (const uint4*)(g_wblob + c_blob_off[grp * 3 + 0]);
    const uint4* W2 = (const uint4*)(g_wblob + c_blob_off[grp * 3 + 1]);
    const uint4* W3 = (const uint4*)(g_wblob + c_blob_off[grp * 3 + 2]);

    // z load (group-private copy) + all biases
    const float* kb = koop + (size_t)b * 4096;
    for (int i = gtid; i < 4096; i += 256) {
        const int l = i >> 6, d = i & 63;
        sA[d * LDA + l] = __float2half_rn(kb[i]);
    }
    for (int i = gtid; i < 512; i += 256) {
        sBias[i] = __ldg(bias1 + i);
        sBias[512 + i] = __ldg(bias2 + i);
        sBias[1024 + i] = __ldg(bias3 + i);
    }
    gbar(barid);

    float acc[2][8][4];
    process_layer<4>(W1, sBias, sA, stg, acc, lane, wm, wnl, gtid, barid);
    process_layer<32>(W2, sBias + 512, sA, stg, acc, lane, wm, wnl, gtid, barid);
    process_layer<32>(W3, sBias + 1024, sA, stg, acc, lane, wm, wnl, gtid, barid);

    // layer 4 diagonal: row r dots W4[:, r]; 4 partials per row
    {
        const int r = gtid & 63, p = gtid >> 6;   // p in 0..3
        float a4 = 0.0f;
        const __half2* hrow = (const __half2*)(sA + r * LDA + p * 128);
        const float* wcol = W4 + (size_t)(p * 128) * 64 + r;
#pragma unroll 8
        for (int i = 0; i < 64; ++i) {
            const float2 hv = __half22float2(hrow[i]);
            a4 += hv.x * __ldg(wcol + (size_t)(2 * i) * 64);
            a4 += hv.y * __ldg(wcol + (size_t)(2 * i + 1) * 64);
        }
        sRed[p * 64 + r] = a4;
        gbar(barid);
        if (gtid < 64)
            sSg[gtid] = sRed[gtid] + sRed[64 + gtid] + sRed[128 + gtid]
                      + sRed[192 + gtid] + __ldg(b4 + gtid);
    }

    __syncthreads();   // cross-group: both diags ready
    if (tid < 64) {
        const float vs = *(const float*)(smem + OFF_S + tid * 4);
        const float vt = *(const float*)(smem + GRP + OFF_S + tid * 4);
        const size_t o = (size_t)b * 64 + tid;
        out[o] = (x[o] - vt) * __expf(-vs);
    }
}

}  // namespace

extern "C" void kernel_launch(void* const* d_in, const int* in_sizes, int n_in,
                              void* d_out, int out_size) {
    (void)in_sizes; (void)n_in; (void)out_size;
    const float* x    = (const float*)d_in[0];
    const float* koop = (const float*)d_in[1];
    const float* sW1 = (const float*)d_in[2];  const float* sb1 = (const float*)d_in[3];
    const float* sW2 = (const float*)d_in[4];  const float* sb2 = (const float*)d_in[5];
    const float* sW3 = (const float*)d_in[6];  const float* sb3 = (const float*)d_in[7];
    const float* sW4 = (const float*)d_in[8];  const float* sb4 = (const float*)d_in[9];
    const float* tW1 = (const float*)d_in[10]; const float* tb1 = (const float*)d_in[11];
    const float* tW2 = (const float*)d_in[12]; const float* tb2 = (const float*)d_in[13];
    const float* tW3 = (const float*)d_in[14]; const float* tb3 = (const float*)d_in[15];
    const float* tW4 = (const float*)d_in[16]; const float* tb4 = (const float*)d_in[17];
    float* out = (float*)d_out;

    prep_kernel<<<(557056 + 255) / 256, 256>>>(sW1, sW2, sW3, tW1, tW2, tW3);

    cudaFuncSetAttribute(decoder_kernel, cudaFuncAttributeMaxDynamicSharedMemorySize,
                         SMEM_BYTES);
    decoder_kernel<<<2048, NTHREADS, SMEM_BYTES>>>(
        x, koop, sb1, sb2, sb3, sW4, sb4,
        tb1, tb2, tb3, tW4, tb4, out);
}

// round 12
// speedup vs baseline: 1.0328x; 1.0328x over previous
#include <cuda_runtime.h>
#include <cuda_fp16.h>
#include <cstdint>

// Decoder: out[b,d] = (x[b,d] - diag_t[b,d]) * exp(-diag_s[b,d])
// R11: 2 batches per CTA (M=128), single 16-warp team, per-warp 4Mx4N tiles.
// B via LDG.128 from fragment-major blob (halved per-warp LDG pressure, halved
// chip L2 traffic), A via ldmatrix from SMEM.

namespace {

constexpr int Hn = 512;
constexpr int LDA = 520;        // A stride in halves (1040 B)
constexpr int NTHREADS = 512;   // 16 warps: 2(wm: 64 rows) x 8(wn: 32 cols/half)

// blob (u32 = f16x2), fragment-major in 16-k chunks: mlp0 L1,L2,L3 then mlp1
__device__ __align__(16) uint32_t g_wblob[557056];
__constant__ int c_blob_off[7] = {0, 16384, 147456, 278528, 294912, 425984, 557056};

// smem byte offsets
constexpr int OFF_STG  = 133120;   // 128 x 264 halves staging (67584 B)
constexpr int OFF_BIAS = 200704;   // 3 x 512 f32 (6144 B)
constexpr int OFF_RED  = 206848;   // 4 x 128 f32 (2048 B)
constexpr int OFF_S    = 208896;   // 128 f32 (512 B)
constexpr int SMEM_BYTES = 209920;

__device__ __forceinline__ void mma16(float c[4], const unsigned a[4],
                                      unsigned b0, unsigned b1) {
    asm volatile(
        "mma.sync.aligned.m16n8k16.row.col.f32.f16.f16.f32 "
        "{%0,%1,%2,%3}, {%4,%5,%6,%7}, {%8,%9}, {%0,%1,%2,%3};"
        : "+f"(c[0]), "+f"(c[1]), "+f"(c[2]), "+f"(c[3])
        : "r"(a[0]), "r"(a[1]), "r"(a[2]), "r"(a[3]), "r"(b0), "r"(b1));
}
__device__ __forceinline__ void ldsm4(unsigned r[4], uint32_t addr) {
    asm volatile("ldmatrix.sync.aligned.m8n8.x4.shared.b16 {%0,%1,%2,%3}, [%4];"
                 : "=r"(r[0]), "=r"(r[1]), "=r"(r[2]), "=r"(r[3]) : "r"(addr));
}
__device__ __forceinline__ void ldg128(uint4& v, const uint4* p) {
    asm volatile("ld.global.nc.v4.u32 {%0,%1,%2,%3}, [%4];"
                 : "=r"(v.x), "=r"(v.y), "=r"(v.z), "=r"(v.w) : "l"(p));
}
__device__ __forceinline__ float fast_tanh(float x) {
    float e = __expf(2.0f * x);
    return 1.0f - __fdividef(2.0f, e + 1.0f);
}
__device__ __forceinline__ uint32_t pack_f16x2(float lo, float hi) {
    uint32_t r;
    asm("cvt.rn.f16x2.f32 %0, %1, %2;" : "=r"(r) : "f"(hi), "f"(lo));
    return r;
}

// ---- fused prep: all 6 hidden-layer weights -> fp16 fragment blob ----
__global__ void prep_kernel(const float* __restrict__ W0, const float* __restrict__ W1,
                            const float* __restrict__ W2, const float* __restrict__ W3,
                            const float* __restrict__ W4, const float* __restrict__ W5) {
    const int eg = blockIdx.x * blockDim.x + threadIdx.x;
    if (eg >= 557056) return;
    const float* srcs[6] = {W0, W1, W2, W3, W4, W5};
    int slot = 0;
    while (eg >= c_blob_off[slot + 1]) ++slot;
    const float* W = srcs[slot];
    const int e = eg - c_blob_off[slot];
    const int q = e & 3;
    const int lane = (e >> 2) & 31;
    const int p = (e >> 7) & 3;
    const int wn = (e >> 9) & 7;
    const int chunk = e >> 12;
    const int k = chunk * 16 + 2 * (lane & 3) + 8 * (q & 1);
    const int col = wn * 64 + (2 * p + (q >> 1)) * 8 + (lane >> 2);
    g_wblob[eg] = pack_f16x2(W[k * Hn + col], W[(k + 1) * Hn + col]);
}

// ---- main ----
__device__ __forceinline__ void load_a4(unsigned a[4][4], uint32_t ab) {
    ldsm4(a[0], ab);
    ldsm4(a[1], ab + 16640);    // +16 rows
    ldsm4(a[2], ab + 33280);
    ldsm4(a[3], ab + 49920);
}
__device__ __forceinline__ void mma_p(float acc[4][4][4], const unsigned a[4][4],
                                      const uint4& bv, int p) {
#pragma unroll
    for (int mt = 0; mt < 4; ++mt) {
        mma16(acc[mt][2 * p],     a[mt], bv.x, bv.y);
        mma16(acc[mt][2 * p + 1], a[mt], bv.z, bv.w);
    }
}

// one 256-col half of a layer; KH = K/16 kh-steps
template <int KH>
__device__ __forceinline__ void gemm_half(const uint4* __restrict__ Wg, int h,
                                          const __half* sA, float acc[4][4][4],
                                          int lane, int wm, int wn) {
#pragma unroll
    for (int mt = 0; mt < 4; ++mt)
#pragma unroll
        for (int nt = 0; nt < 4; ++nt)
#pragma unroll
            for (int q = 0; q < 4; ++q) acc[mt][nt][q] = 0.0f;

    // warp covers cols h*256 + wn*32 .. +31  ->  blob wn' = h*4 + (wn>>1),
    // p-block offset (wn&1)*2  ->  uint4 offset (wn&1)*64
    const uint4* bp = Wg + (h * 4 + (wn >> 1)) * 128 + (wn & 1) * 64 + lane;
    const int arow = wm * 64 + (lane & 15);
    const int acol = (lane >> 4) * 8;
    uint32_t ab = (unsigned)__cvta_generic_to_shared(sA + arow * LDA + acol);

    uint4 b[2][2];
    ldg128(b[0][0], bp);
    ldg128(b[0][1], bp + 32);
    ldg128(b[1][0], bp + 1024);
    ldg128(b[1][1], bp + 1056);

#pragma unroll 2
    for (int kh = 0; kh < KH - 2; ++kh) {
        const int s = kh & 1;
        unsigned a[4][4];
        load_a4(a, ab);
        mma_p(acc, a, b[s][0], 0);
        ldg128(b[s][0], bp + (size_t)(kh + 2) * 1024);
        mma_p(acc, a, b[s][1], 1);
        ldg128(b[s][1], bp + (size_t)(kh + 2) * 1024 + 32);
        ab += 32;
    }
    {
        unsigned a[4][4];
        load_a4(a, ab);
        mma_p(acc, a, b[(KH - 2) & 1][0], 0);
        mma_p(acc, a, b[(KH - 2) & 1][1], 1);
        ab += 32;
        load_a4(a, ab);
        mma_p(acc, a, b[(KH - 1) & 1][0], 0);
        mma_p(acc, a, b[(KH - 1) & 1][1], 1);
    }
}

// tanh(acc+bias) half 0 -> staging (stride 264 halves), cols 0..255
__device__ __forceinline__ void store_stg(const float acc[4][4][4], char* stg,
                                          const float* lb, int lane, int wm, int wn) {
    const int g8 = lane >> 2, t4 = lane & 3;
#pragma unroll
    for (int mt = 0; mt < 4; ++mt) {
        const int row0 = wm * 64 + mt * 16 + g8;
#pragma unroll
        for (int nt = 0; nt < 4; ++nt) {
            const int col = wn * 32 + nt * 8 + 2 * t4;
            const float b0 = lb[col], b1 = lb[col + 1];
            *(uint32_t*)(stg + (row0 * 264 + col) * 2) =
                pack_f16x2(fast_tanh(acc[mt][nt][0] + b0), fast_tanh(acc[mt][nt][1] + b1));
            *(uint32_t*)(stg + ((row0 + 8) * 264 + col) * 2) =
                pack_f16x2(fast_tanh(acc[mt][nt][2] + b0), fast_tanh(acc[mt][nt][3] + b1));
        }
    }
}
// tanh(acc+bias) half 1 -> sA cols 256..511
__device__ __forceinline__ void store_hi(const float acc[4][4][4], __half* sA,
                                         const float* lb, int lane, int wm, int wn) {
    const int g8 = lane >> 2, t4 = lane & 3;
#pragma unroll
    for (int mt = 0; mt < 4; ++mt) {
        const int row0 = wm * 64 + mt * 16 + g8;
#pragma unroll
        for (int nt = 0; nt < 4; ++nt) {
            const int col = 256 + wn * 32 + nt * 8 + 2 * t4;
            const float b0 = lb[col], b1 = lb[col + 1];
            *(uint32_t*)(sA + row0 * LDA + col) =
                pack_f16x2(fast_tanh(acc[mt][nt][0] + b0), fast_tanh(acc[mt][nt][1] + b1));
            *(uint32_t*)(sA + (row0 + 8) * LDA + col) =
                pack_f16x2(fast_tanh(acc[mt][nt][2] + b0), fast_tanh(acc[mt][nt][3] + b1));
        }
    }
}

template <int KH>
__device__ __forceinline__ void process_layer(const uint4* __restrict__ Wg,
                                              const float* lb, __half* sA, char* stg,
                                              float acc[4][4][4], int tid, int lane,
                                              int wm, int wn) {
    gemm_half<KH>(Wg, 0, sA, acc, lane, wm, wn);
    store_stg(acc, stg, lb, lane, wm, wn);
    gemm_half<KH>(Wg, 1, sA, acc, lane, wm, wn);
    __syncthreads();   // all A reads done; stg writes visible
    store_hi(acc, sA, lb, lane, wm, wn);
#pragma unroll
    for (int j = 0; j < 8; ++j) {   // copy stg -> sA cols 0..255 (128x512B)
        const int f4 = tid + j * 512;
        const int row = f4 >> 5, c = f4 & 31;
        *(uint4*)((char*)sA + row * 1040 + c * 16) =
            *(const uint4*)(stg + row * 528 + c * 16);
    }
    __syncthreads();   // sA ready for next layer
}

__global__ __launch_bounds__(NTHREADS, 1)
void decoder_kernel(const float* __restrict__ x, const float* __restrict__ koop,
                    const float* __restrict__ sb1, const float* __restrict__ sb2,
                    const float* __restrict__ sb3,
                    const float* __restrict__ sW4, const float* __restrict__ sb4,
                    const float* __restrict__ tb1, const float* __restrict__ tb2,
                    const float* __restrict__ tb3,
                    const float* __restrict__ tW4, const float* __restrict__ tb4,
                    float* __restrict__ out) {
    extern __shared__ char smem[];
    __half* sA = (__half*)smem;
    char* stg = smem + OFF_STG;
    float* sBias = (float*)(smem + OFF_BIAS);
    float* sRed = (float*)(smem + OFF_RED);
    float* sS = (float*)(smem + OFF_S);

    const int tid = threadIdx.x, lane = tid & 31, wid = tid >> 5;
    const int wm = wid >> 3;   // 0..1 (64 rows each)
    const int wn = wid & 7;    // 0..7 (32 cols each per half)
    const int b0 = blockIdx.x * 2;

    float acc[4][4][4];

#pragma unroll 1
    for (int mlp = 0; mlp < 2; ++mlp) {
        const uint4* W1 = (const uint4*)(g_wblob + c_blob_off[mlp * 3 + 0]);
        const uint4* W2 = (const uint4*)(g_wblob + c_blob_off[mlp * 3 + 1]);
        const uint4* W3 = (const uint4*)(g_wblob + c_blob_off[mlp * 3 + 2]);
        const float* bias1 = mlp ? tb1 : sb1;
        const float* bias2 = mlp ? tb2 : sb2;
        const float* bias3 = mlp ? tb3 : sb3;
        const float* W4 = mlp ? tW4 : sW4;
        const float* b4 = mlp ? tb4 : sb4;

        // z load: rows (bb*64+d), cols l  <-  koopman[b0+bb, l, d]
        const float* kb = koop + (size_t)b0 * 4096;
        for (int i = tid; i < 8192; i += NTHREADS) {
            const int bb = i >> 12, l = (i >> 6) & 63, d = i & 63;
            sA[(bb * 64 + d) * LDA + l] =
                __float2half_rn(kb[(size_t)bb * 4096 + l * 64 + d]);
        }
        sBias[tid]        = __ldg(bias1 + tid);
        sBias[512 + tid]  = __ldg(bias2 + tid);
        sBias[1024 + tid] = __ldg(bias3 + tid);
        __syncthreads();

        process_layer<4>(W1, sBias, sA, stg, acc, tid, lane, wm, wn);
        process_layer<32>(W2, sBias + 512, sA, stg, acc, tid, lane, wm, wn);
        process_layer<32>(W3, sBias + 1024, sA, stg, acc, tid, lane, wm, wn);

        // layer 4 diagonal: row r (0..127) dots W4[:, r&63]; 4 partials/row
        const int r = tid & 127, p = tid >> 7;   // p in 0..3
        float a4 = 0.0f;
        const __half2* hrow = (const __half2*)(sA + r * LDA + p * 128);
        const float* wcol = W4 + (size_t)(p * 128) * 64 + (r & 63);
#pragma unroll 8
        for (int i = 0; i < 64; ++i) {
            const float2 hv = __half22float2(hrow[i]);
            a4 += hv.x * __ldg(wcol + (size_t)(2 * i) * 64);
            a4 += hv.y * __ldg(wcol + (size_t)(2 * i + 1) * 64);
        }
        sRed[p * 128 + r] = a4;
        __syncthreads();
        if (tid < 128) {
            const float v = sRed[tid] + sRed[128 + tid] + sRed[256 + tid]
                          + sRed[384 + tid] + __ldg(b4 + (tid & 63));
            if (mlp == 0) {
                sS[tid] = v;
            } else {
                const size_t o = (size_t)b0 * 64 + tid;
                out[o] = (x[o] - v) * __expf(-sS[tid]);
            }
        }
        __syncthreads();   // sRed/sS settled before next mlp reuses them
    }
}

}  // namespace

extern "C" void kernel_launch(void* const* d_in, const int* in_sizes, int n_in,
                              void* d_out, int out_size) {
    (void)in_sizes; (void)n_in; (void)out_size;
    const float* x    = (const float*)d_in[0];
    const float* koop = (const float*)d_in[1];
    const float* sW1 = (const float*)d_in[2];  const float* sb1 = (const float*)d_in[3];
    const float* sW2 = (const float*)d_in[4];  const float* sb2 = (const float*)d_in[5];
    const float* sW3 = (const float*)d_in[6];  const float* sb3 = (const float*)d_in[7];
    const float* sW4 = (const float*)d_in[8];  const float* sb4 = (const float*)d_in[9];
    const float* tW1 = (const float*)d_in[10]; const float* tb1 = (const float*)d_in[11];
    const float* tW2 = (const float*)d_in[12]; const float* tb2 = (const float*)d_in[13];
    const float* tW3 = (const float*)d_in[14]; const float* tb3 = (const float*)d_in[15];
    const float* tW4 = (const float*)d_in[16]; const float* tb4 = (const float*)d_in[17];
    float* out = (float*)d_out;

    prep_kernel<<<(557056 + 255) / 256, 256>>>(sW1, sW2, sW3, tW1, tW2, tW3);

    cudaFuncSetAttribute(decoder_kernel, cudaFuncAttributeMaxDynamicSharedMemorySize,
                         SMEM_BYTES);
    decoder_kernel<<<1024, NTHREADS, SMEM_BYTES>>>(
        x, koop, sb1, sb2, sb3, sW4, sb4,
        tb1, tb2, tb3, tW4, tb4, out);
}

// round 13
// speedup vs baseline: 1.0588x; 1.0252x over previous
#include <cuda_runtime.h>
#include <cuda_fp16.h>
#include <cstdint>

// Decoder: out[b,d] = (x[b,d] - diag_t[b,d]) * exp(-diag_s[b,d])
// R12 = R11 (M=128, 2 batches/CTA, 16 warps, 4Mx4N tiles, B via LDG.128)
//  + A-fragment double buffering (ldmatrix issued one kh-step ahead)
//  + hardware tanh.approx.f32 (1 MUFU instead of EX2+RCP+FMAs)

namespace {

constexpr int Hn = 512;
constexpr int LDA = 520;        // A stride in halves (1040 B)
constexpr int NTHREADS = 512;   // 16 warps: 2(wm: 64 rows) x 8(wn: 32 cols/half)

// blob (u32 = f16x2), fragment-major in 16-k chunks: mlp0 L1,L2,L3 then mlp1
__device__ __align__(16) uint32_t g_wblob[557056];
__constant__ int c_blob_off[7] = {0, 16384, 147456, 278528, 294912, 425984, 557056};

// smem byte offsets
constexpr int OFF_STG  = 133120;   // 128 x 264 halves staging (67584 B)
constexpr int OFF_BIAS = 200704;   // 3 x 512 f32 (6144 B)
constexpr int OFF_RED  = 206848;   // 4 x 128 f32 (2048 B)
constexpr int OFF_S    = 208896;   // 128 f32 (512 B)
constexpr int SMEM_BYTES = 209920;

__device__ __forceinline__ void mma16(float c[4], const unsigned a[4],
                                      unsigned b0, unsigned b1) {
    asm volatile(
        "mma.sync.aligned.m16n8k16.row.col.f32.f16.f16.f32 "
        "{%0,%1,%2,%3}, {%4,%5,%6,%7}, {%8,%9}, {%0,%1,%2,%3};"
        : "+f"(c[0]), "+f"(c[1]), "+f"(c[2]), "+f"(c[3])
        : "r"(a[0]), "r"(a[1]), "r"(a[2]), "r"(a[3]), "r"(b0), "r"(b1));
}
__device__ __forceinline__ void ldsm4(unsigned r[4], uint32_t addr) {
    asm volatile("ldmatrix.sync.aligned.m8n8.x4.shared.b16 {%0,%1,%2,%3}, [%4];"
                 : "=r"(r[0]), "=r"(r[1]), "=r"(r[2]), "=r"(r[3]) : "r"(addr));
}
__device__ __forceinline__ void ldg128(uint4& v, const uint4* p) {
    asm volatile("ld.global.nc.v4.u32 {%0,%1,%2,%3}, [%4];"
                 : "=r"(v.x), "=r"(v.y), "=r"(v.z), "=r"(v.w) : "l"(p));
}
// hardware tanh approximation (sm_75+), max abs err ~5e-4
__device__ __forceinline__ float htanh(float x) {
    float y;
    asm("tanh.approx.f32 %0, %1;" : "=f"(y) : "f"(x));
    return y;
}
__device__ __forceinline__ uint32_t pack_f16x2(float lo, float hi) {
    uint32_t r;
    asm("cvt.rn.f16x2.f32 %0, %1, %2;" : "=r"(r) : "f"(hi), "f"(lo));
    return r;
}

// ---- fused prep: all 6 hidden-layer weights -> fp16 fragment blob ----
__global__ void prep_kernel(const float* __restrict__ W0, const float* __restrict__ W1,
                            const float* __restrict__ W2, const float* __restrict__ W3,
                            const float* __restrict__ W4, const float* __restrict__ W5) {
    const int eg = blockIdx.x * blockDim.x + threadIdx.x;
    if (eg >= 557056) return;
    const float* srcs[6] = {W0, W1, W2, W3, W4, W5};
    int slot = 0;
    while (eg >= c_blob_off[slot + 1]) ++slot;
    const float* W = srcs[slot];
    const int e = eg - c_blob_off[slot];
    const int q = e & 3;
    const int lane = (e >> 2) & 31;
    const int p = (e >> 7) & 3;
    const int wn = (e >> 9) & 7;
    const int chunk = e >> 12;
    const int k = chunk * 16 + 2 * (lane & 3) + 8 * (q & 1);
    const int col = wn * 64 + (2 * p + (q >> 1)) * 8 + (lane >> 2);
    float v0 = W[k * Hn + col], v1 = W[(k + 1) * Hn + col];
    uint32_t r;
    asm("cvt.rn.f16x2.f32 %0, %1, %2;" : "=r"(r) : "f"(v1), "f"(v0));
    g_wblob[eg] = r;
}

// ---- main ----
__device__ __forceinline__ void load_a4(unsigned a[4][4], uint32_t ab) {
    ldsm4(a[0], ab);
    ldsm4(a[1], ab + 16640);    // +16 rows
    ldsm4(a[2], ab + 33280);
    ldsm4(a[3], ab + 49920);
}
__device__ __forceinline__ void mma_p(float acc[4][4][4], const unsigned a[4][4],
                                      const uint4& bv, int p) {
#pragma unroll
    for (int mt = 0; mt < 4; ++mt) {
        mma16(acc[mt][2 * p],     a[mt], bv.x, bv.y);
        mma16(acc[mt][2 * p + 1], a[mt], bv.z, bv.w);
    }
}

// one 256-col half of a layer; KH = K/16 kh-steps
template <int KH>
__device__ __forceinline__ void gemm_half(const uint4* __restrict__ Wg, int h,
                                          const __half* sA, float acc[4][4][4],
                                          int lane, int wm, int wn) {
#pragma unroll
    for (int mt = 0; mt < 4; ++mt)
#pragma unroll
        for (int nt = 0; nt < 4; ++nt)
#pragma unroll
            for (int q = 0; q < 4; ++q) acc[mt][nt][q] = 0.0f;

    const uint4* bp = Wg + (h * 4 + (wn >> 1)) * 128 + (wn & 1) * 64 + lane;
    const int arow = wm * 64 + (lane & 15);
    const int acol = (lane >> 4) * 8;
    const uint32_t ab = (unsigned)__cvta_generic_to_shared(sA + arow * LDA + acol);

    unsigned a[2][4][4];
    uint4 b[2][2];
    load_a4(a[0], ab);
    ldg128(b[0][0], bp);
    ldg128(b[0][1], bp + 32);
    ldg128(b[1][0], bp + 1024);
    ldg128(b[1][1], bp + 1056);

#pragma unroll 2
    for (int kh = 0; kh < KH; ++kh) {
        const int s = kh & 1;
        if (kh + 1 < KH) load_a4(a[s ^ 1], ab + (kh + 1) * 32);
        mma_p(acc, a[s], b[s][0], 0);
        if (kh + 2 < KH) ldg128(b[s][0], bp + (size_t)(kh + 2) * 1024);
        mma_p(acc, a[s], b[s][1], 1);
        if (kh + 2 < KH) ldg128(b[s][1], bp + (size_t)(kh + 2) * 1024 + 32);
    }
}

// tanh(acc+bias) half 0 -> staging (stride 264 halves), cols 0..255
__device__ __forceinline__ void store_stg(const float acc[4][4][4], char* stg,
                                          const float* lb, int lane, int wm, int wn) {
    const int g8 = lane >> 2, t4 = lane & 3;
#pragma unroll
    for (int mt = 0; mt < 4; ++mt) {
        const int row0 = wm * 64 + mt * 16 + g8;
#pragma unroll
        for (int nt = 0; nt < 4; ++nt) {
            const int col = wn * 32 + nt * 8 + 2 * t4;
            const float b0 = lb[col], b1 = lb[col + 1];
            *(uint32_t*)(stg + (row0 * 264 + col) * 2) =
                pack_f16x2(htanh(acc[mt][nt][0] + b0), htanh(acc[mt][nt][1] + b1));
            *(uint32_t*)(stg + ((row0 + 8) * 264 + col) * 2) =
                pack_f16x2(htanh(acc[mt][nt][2] + b0), htanh(acc[mt][nt][3] + b1));
        }
    }
}
// tanh(acc+bias) half 1 -> sA cols 256..511
__device__ __forceinline__ void store_hi(const float acc[4][4][4], __half* sA,
                                         const float* lb, int lane, int wm, int wn) {
    const int g8 = lane >> 2, t4 = lane & 3;
#pragma unroll
    for (int mt = 0; mt < 4; ++mt) {
        const int row0 = wm * 64 + mt * 16 + g8;
#pragma unroll
        for (int nt = 0; nt < 4; ++nt) {
            const int col = 256 + wn * 32 + nt * 8 + 2 * t4;
            const float b0 = lb[col], b1 = lb[col + 1];
            *(uint32_t*)(sA + row0 * LDA + col) =
                pack_f16x2(htanh(acc[mt][nt][0] + b0), htanh(acc[mt][nt][1] + b1));
            *(uint32_t*)(sA + (row0 + 8) * LDA + col) =
                pack_f16x2(htanh(acc[mt][nt][2] + b0), htanh(acc[mt][nt][3] + b1));
        }
    }
}

template <int KH>
__device__ __forceinline__ void process_layer(const uint4* __restrict__ Wg,
                                              const float* lb, __half* sA, char* stg,
                                              float acc[4][4][4], int tid, int lane,
                                              int wm, int wn) {
    gemm_half<KH>(Wg, 0, sA, acc, lane, wm, wn);
    store_stg(acc, stg, lb, lane, wm, wn);
    gemm_half<KH>(Wg, 1, sA, acc, lane, wm, wn);
    __syncthreads();   // all A reads done; stg writes visible
    store_hi(acc, sA, lb, lane, wm, wn);
#pragma unroll
    for (int j = 0; j < 8; ++j) {   // copy stg -> sA cols 0..255 (128x512B)
        const int f4 = tid + j * 512;
        const int row = f4 >> 5, c = f4 & 31;
        *(uint4*)((char*)sA + row * 1040 + c * 16) =
            *(const uint4*)(stg + row * 528 + c * 16);
    }
    __syncthreads();   // sA ready for next layer
}

__global__ __launch_bounds__(NTHREADS, 1)
void decoder_kernel(const float* __restrict__ x, const float* __restrict__ koop,
                    const float* __restrict__ sb1, const float* __restrict__ sb2,
                    const float* __restrict__ sb3,
                    const float* __restrict__ sW4, const float* __restrict__ sb4,
                    const float* __restrict__ tb1, const float* __restrict__ tb2,
                    const float* __restrict__ tb3,
                    const float* __restrict__ tW4, const float* __restrict__ tb4,
                    float* __restrict__ out) {
    extern __shared__ char smem[];
    __half* sA = (__half*)smem;
    char* stg = smem + OFF_STG;
    float* sBias = (float*)(smem + OFF_BIAS);
    float* sRed = (float*)(smem + OFF_RED);
    float* sS = (float*)(smem + OFF_S);

    const int tid = threadIdx.x, lane = tid & 31, wid = tid >> 5;
    const int wm = wid >> 3;   // 0..1 (64 rows each)
    const int wn = wid & 7;    // 0..7 (32 cols each per half)
    const int b0 = blockIdx.x * 2;

    float acc[4][4][4];

#pragma unroll 1
    for (int mlp = 0; mlp < 2; ++mlp) {
        const uint4* W1 = (const uint4*)(g_wblob + c_blob_off[mlp * 3 + 0]);
        const uint4* W2 = (const uint4*)(g_wblob + c_blob_off[mlp * 3 + 1]);
        const uint4* W3 = (const uint4*)(g_wblob + c_blob_off[mlp * 3 + 2]);
        const float* bias1 = mlp ? tb1 : sb1;
        const float* bias2 = mlp ? tb2 : sb2;
        const float* bias3 = mlp ? tb3 : sb3;
        const float* W4 = mlp ? tW4 : sW4;
        const float* b4 = mlp ? tb4 : sb4;

        // z load: rows (bb*64+d), cols l  <-  koopman[b0+bb, l, d]
        const float* kb = koop + (size_t)b0 * 4096;
        for (int i = tid; i < 8192; i += NTHREADS) {
            const int bb = i >> 12, l = (i >> 6) & 63, d = i & 63;
            sA[(bb * 64 + d) * LDA + l] =
                __float2half_rn(kb[(size_t)bb * 4096 + l * 64 + d]);
        }
        sBias[tid]        = __ldg(bias1 + tid);
        sBias[512 + tid]  = __ldg(bias2 + tid);
        sBias[1024 + tid] = __ldg(bias3 + tid);
        __syncthreads();

        process_layer<4>(W1, sBias, sA, stg, acc, tid, lane, wm, wn);
        process_layer<32>(W2, sBias + 512, sA, stg, acc, tid, lane, wm, wn);
        process_layer<32>(W3, sBias + 1024, sA, stg, acc, tid, lane, wm, wn);

        // layer 4 diagonal: row r (0..127) dots W4[:, r&63]; 4 partials/row
        const int r = tid & 127, p = tid >> 7;   // p in 0..3
        float a4 = 0.0f;
        const __half2* hrow = (const __half2*)(sA + r * LDA + p * 128);
        const float* wcol = W4 + (size_t)(p * 128) * 64 + (r & 63);
#pragma unroll 8
        for (int i = 0; i < 64; ++i) {
            const float2 hv = __half22float2(hrow[i]);
            a4 += hv.x * __ldg(wcol + (size_t)(2 * i) * 64);
            a4 += hv.y * __ldg(wcol + (size_t)(2 * i + 1) * 64);
        }
        sRed[p * 128 + r] = a4;
        __syncthreads();
        if (tid < 128) {
            const float v = sRed[tid] + sRed[128 + tid] + sRed[256 + tid]
                          + sRed[384 + tid] + __ldg(b4 + (tid & 63));
            if (mlp == 0) {
                sS[tid] = v;
            } else {
                const size_t o = (size_t)b0 * 64 + tid;
                out[o] = (x[o] - v) * __expf(-sS[tid]);
            }
        }
        __syncthreads();   // sRed/sS settled before next mlp reuses them
    }
}

}  // namespace

extern "C" void kernel_launch(void* const* d_in, const int* in_sizes, int n_in,
                              void* d_out, int out_size) {
    (void)in_sizes; (void)n_in; (void)out_size;
    const float* x    = (const float*)d_in[0];
    const float* koop = (const float*)d_in[1];
    const float* sW1 = (const float*)d_in[2];  const float* sb1 = (const float*)d_in[3];
    const float* sW2 = (const float*)d_in[4];  const float* sb2 = (const float*)d_in[5];
    const float* sW3 = (const float*)d_in[6];  const float* sb3 = (const float*)d_in[7];
    const float* sW4 = (const float*)d_in[8];  const float* sb4 = (const float*)d_in[9];
    const float* tW1 = (const float*)d_in[10]; const float* tb1 = (const float*)d_in[11];
    const float* tW2 = (const float*)d_in[12]; const float* tb2 = (const float*)d_in[13];
    const float* tW3 = (const float*)d_in[14]; const float* tb3 = (const float*)d_in[15];
    const float* tW4 = (const float*)d_in[16]; const float* tb4 = (const float*)d_in[17];
    float* out = (float*)d_out;

    prep_kernel<<<(557056 + 255) / 256, 256>>>(sW1, sW2, sW3, tW1, tW2, tW3);

    cudaFuncSetAttribute(decoder_kernel, cudaFuncAttributeMaxDynamicSharedMemorySize,
                         SMEM_BYTES);
    decoder_kernel<<<1024, NTHREADS, SMEM_BYTES>>>(
        x, koop, sb1, sb2, sb3, sW4, sb4,
        tb1, tb2, tb3, tW4, tb4, out);
}

// round 14
// speedup vs baseline: 1.1787x; 1.1132x over previous
#include <cuda_runtime.h>
#include <cuda_fp16.h>
#include <cstdint>

// Decoder: out[b,d] = (x[b,d] - diag_t[b,d]) * exp(-diag_s[b,d])
// R13: M=64 per CTA (256 threads, 8 warps, 2wm x 4wn), SMEM 105KB ->
// 2 CTAs/SM co-resident; hardware scheduler desyncs their epilogues so the
// tensor pipe stays fed. Keeps R12's A/B register double-buffer + htanh.

namespace {

constexpr int Hn = 512;
constexpr int LDA = 520;        // A stride in halves (1040 B)
constexpr int NTHREADS = 256;   // 8 warps: 2(wm: 32 rows) x 4(wn: 64 cols/half)

// blob (u32 = f16x2), fragment-major in 16-k chunks: mlp0 L1,L2,L3 then mlp1
__device__ __align__(16) uint32_t g_wblob[557056];
__constant__ int c_blob_off[7] = {0, 16384, 147456, 278528, 294912, 425984, 557056};

// smem byte offsets
constexpr int OFF_STG  = 66560;    // 64 x 264 halves staging (33792 B)
constexpr int OFF_BIAS = 100352;   // 3 x 512 f32 (6144 B)
constexpr int OFF_RED  = 106496;   // 4 x 64 f32 (1024 B)
constexpr int OFF_S    = 107520;   // 64 f32 (256 B)
constexpr int SMEM_BYTES = 107776; // 105.25 KB -> 2 CTAs/SM

__device__ __forceinline__ void mma16(float c[4], const unsigned a[4],
                                      unsigned b0, unsigned b1) {
    asm volatile(
        "mma.sync.aligned.m16n8k16.row.col.f32.f16.f16.f32 "
        "{%0,%1,%2,%3}, {%4,%5,%6,%7}, {%8,%9}, {%0,%1,%2,%3};"
        : "+f"(c[0]), "+f"(c[1]), "+f"(c[2]), "+f"(c[3])
        : "r"(a[0]), "r"(a[1]), "r"(a[2]), "r"(a[3]), "r"(b0), "r"(b1));
}
__device__ __forceinline__ void ldsm4(unsigned r[4], uint32_t addr) {
    asm volatile("ldmatrix.sync.aligned.m8n8.x4.shared.b16 {%0,%1,%2,%3}, [%4];"
                 : "=r"(r[0]), "=r"(r[1]), "=r"(r[2]), "=r"(r[3]) : "r"(addr));
}
__device__ __forceinline__ void ldg128(uint4& v, const uint4* p) {
    asm volatile("ld.global.nc.v4.u32 {%0,%1,%2,%3}, [%4];"
                 : "=r"(v.x), "=r"(v.y), "=r"(v.z), "=r"(v.w) : "l"(p));
}
// hardware tanh approximation (sm_75+), max abs err ~5e-4
__device__ __forceinline__ float htanh(float x) {
    float y;
    asm("tanh.approx.f32 %0, %1;" : "=f"(y) : "f"(x));
    return y;
}
__device__ __forceinline__ uint32_t pack_f16x2(float lo, float hi) {
    uint32_t r;
    asm("cvt.rn.f16x2.f32 %0, %1, %2;" : "=r"(r) : "f"(hi), "f"(lo));
    return r;
}

// ---- fused prep: all 6 hidden-layer weights -> fp16 fragment blob ----
__global__ void prep_kernel(const float* __restrict__ W0, const float* __restrict__ W1,
                            const float* __restrict__ W2, const float* __restrict__ W3,
                            const float* __restrict__ W4, const float* __restrict__ W5) {
    const int eg = blockIdx.x * blockDim.x + threadIdx.x;
    if (eg >= 557056) return;
    const float* srcs[6] = {W0, W1, W2, W3, W4, W5};
    int slot = 0;
    while (eg >= c_blob_off[slot + 1]) ++slot;
    const float* W = srcs[slot];
    const int e = eg - c_blob_off[slot];
    const int q = e & 3;
    const int lane = (e >> 2) & 31;
    const int p = (e >> 7) & 3;
    const int wn = (e >> 9) & 7;
    const int chunk = e >> 12;
    const int k = chunk * 16 + 2 * (lane & 3) + 8 * (q & 1);
    const int col = wn * 64 + (2 * p + (q >> 1)) * 8 + (lane >> 2);
    float v0 = W[k * Hn + col], v1 = W[(k + 1) * Hn + col];
    uint32_t r;
    asm("cvt.rn.f16x2.f32 %0, %1, %2;" : "=r"(r) : "f"(v1), "f"(v0));
    g_wblob[eg] = r;
}

// ---- main ----
__device__ __forceinline__ void load_a2(unsigned a[2][4], uint32_t ab) {
    ldsm4(a[0], ab);
    ldsm4(a[1], ab + 16 * LDA * 2);   // +16 rows
}

// one 256-col half of a layer; KH = K/16 kh-steps; warp covers 64 cols
template <int KH>
__device__ __forceinline__ void gemm_half(const uint4* __restrict__ Wg, int h,
                                          const __half* sA, float acc[2][8][4],
                                          int lane, int wm, int wnl) {
#pragma unroll
    for (int m = 0; m < 2; ++m)
#pragma unroll
        for (int n = 0; n < 8; ++n)
#pragma unroll
            for (int q = 0; q < 4; ++q) acc[m][n][q] = 0.0f;

    const uint4* bp = Wg + (h * 4 + wnl) * 128 + lane;
    const int arow = wm * 32 + (lane & 15);
    const int acol = (lane >> 4) * 8;
    const uint32_t ab = (unsigned)__cvta_generic_to_shared(sA + arow * LDA + acol);

    unsigned a[2][2][4];
    uint4 b[2][4];
    load_a2(a[0], ab);
#pragma unroll
    for (int p = 0; p < 4; ++p) ldg128(b[0][p], bp + p * 32);
#pragma unroll
    for (int p = 0; p < 4; ++p) ldg128(b[1][p], bp + 1024 + p * 32);

#pragma unroll 2
    for (int kh = 0; kh < KH; ++kh) {
        const int s = kh & 1;
        if (kh + 1 < KH) load_a2(a[s ^ 1], ab + (kh + 1) * 32);
#pragma unroll
        for (int p = 0; p < 4; ++p) {
            mma16(acc[0][2 * p],     a[s][0], b[s][p].x, b[s][p].y);
            mma16(acc[1][2 * p],     a[s][1], b[s][p].x, b[s][p].y);
            mma16(acc[0][2 * p + 1], a[s][0], b[s][p].z, b[s][p].w);
            mma16(acc[1][2 * p + 1], a[s][1], b[s][p].z, b[s][p].w);
            if (kh + 2 < KH) ldg128(b[s][p], bp + (size_t)(kh + 2) * 1024 + p * 32);
        }
    }
}

// tanh(acc+bias) half 0 -> staging (stride 264 halves), cols 0..255
__device__ __forceinline__ void store_stg(const float acc[2][8][4], char* stg,
                                          const float* lb, int lane, int wm, int wnl) {
    const int g8 = lane >> 2, t4 = lane & 3;
#pragma unroll
    for (int m = 0; m < 2; ++m) {
        const int row0 = wm * 32 + m * 16 + g8;
#pragma unroll
        for (int n = 0; n < 8; ++n) {
            const int col = wnl * 64 + n * 8 + 2 * t4;
            const float b0 = lb[col], b1 = lb[col + 1];
            *(uint32_t*)(stg + (row0 * 264 + col) * 2) =
                pack_f16x2(htanh(acc[m][n][0] + b0), htanh(acc[m][n][1] + b1));
            *(uint32_t*)(stg + ((row0 + 8) * 264 + col) * 2) =
                pack_f16x2(htanh(acc[m][n][2] + b0), htanh(acc[m][n][3] + b1));
        }
    }
}
// tanh(acc+bias) half 1 -> sA cols 256..511
__device__ __forceinline__ void store_hi(const float acc[2][8][4], __half* sA,
                                         const float* lb, int lane, int wm, int wnl) {
    const int g8 = lane >> 2, t4 = lane & 3;
#pragma unroll
    for (int m = 0; m < 2; ++m) {
        const int row0 = wm * 32 + m * 16 + g8;
#pragma unroll
        for (int n = 0; n < 8; ++n) {
            const int col = 256 + wnl * 64 + n * 8 + 2 * t4;
            const float b0 = lb[col], b1 = lb[col + 1];
            *(uint32_t*)(sA + row0 * LDA + col) =
                pack_f16x2(htanh(acc[m][n][0] + b0), htanh(acc[m][n][1] + b1));
            *(uint32_t*)(sA + (row0 + 8) * LDA + col) =
                pack_f16x2(htanh(acc[m][n][2] + b0), htanh(acc[m][n][3] + b1));
        }
    }
}

template <int KH>
__device__ __forceinline__ void process_layer(const uint4* __restrict__ Wg,
                                              const float* lb, __half* sA, char* stg,
                                              float acc[2][8][4], int tid, int lane,
                                              int wm, int wnl) {
    gemm_half<KH>(Wg, 0, sA, acc, lane, wm, wnl);
    store_stg(acc, stg, lb, lane, wm, wnl);
    gemm_half<KH>(Wg, 1, sA, acc, lane, wm, wnl);
    __syncthreads();   // all A reads done; stg writes visible
    store_hi(acc, sA, lb, lane, wm, wnl);
#pragma unroll
    for (int j = 0; j < 8; ++j) {   // copy stg -> sA cols 0..255 (64 rows x 512B)
        const int f4 = tid + j * 256;
        const int row = f4 >> 5, c = f4 & 31;
        *(uint4*)((char*)sA + row * 1040 + c * 16) =
            *(const uint4*)(stg + row * 528 + c * 16);
    }
    __syncthreads();   // sA ready for next layer
}

__global__ __launch_bounds__(NTHREADS, 2)
void decoder_kernel(const float* __restrict__ x, const float* __restrict__ koop,
                    const float* __restrict__ sb1, const float* __restrict__ sb2,
                    const float* __restrict__ sb3,
                    const float* __restrict__ sW4, const float* __restrict__ sb4,
                    const float* __restrict__ tb1, const float* __restrict__ tb2,
                    const float* __restrict__ tb3,
                    const float* __restrict__ tW4, const float* __restrict__ tb4,
                    float* __restrict__ out) {
    extern __shared__ char smem[];
    __half* sA = (__half*)smem;
    char* stg = smem + OFF_STG;
    float* sBias = (float*)(smem + OFF_BIAS);
    float* sRed = (float*)(smem + OFF_RED);
    float* sS = (float*)(smem + OFF_S);

    const int tid = threadIdx.x, lane = tid & 31, wid = tid >> 5;
    const int wm = wid >> 2;    // 0..1 (32 rows each)
    const int wnl = wid & 3;    // 0..3 (64 cols each per half)
    const int b = blockIdx.x;

    float acc[2][8][4];

#pragma unroll 1
    for (int mlp = 0; mlp < 2; ++mlp) {
        const uint4* W1 = (const uint4*)(g_wblob + c_blob_off[mlp * 3 + 0]);
        const uint4* W2 = (const uint4*)(g_wblob + c_blob_off[mlp * 3 + 1]);
        const uint4* W3 = (const uint4*)(g_wblob + c_blob_off[mlp * 3 + 2]);
        const float* bias1 = mlp ? tb1 : sb1;
        const float* bias2 = mlp ? tb2 : sb2;
        const float* bias3 = mlp ? tb3 : sb3;
        const float* W4 = mlp ? tW4 : sW4;
        const float* b4 = mlp ? tb4 : sb4;

        // z load: sA[d][l] = koopman[b, l, d] as f16
        const float* kb = koop + (size_t)b * 4096;
        for (int i = tid; i < 4096; i += NTHREADS) {
            const int l = i >> 6, d = i & 63;
            sA[d * LDA + l] = __float2half_rn(kb[i]);
        }
        for (int i = tid; i < 512; i += NTHREADS) {
            sBias[i]        = __ldg(bias1 + i);
            sBias[512 + i]  = __ldg(bias2 + i);
            sBias[1024 + i] = __ldg(bias3 + i);
        }
        __syncthreads();

        process_layer<4>(W1, sBias, sA, stg, acc, tid, lane, wm, wnl);
        process_layer<32>(W2, sBias + 512, sA, stg, acc, tid, lane, wm, wnl);
        process_layer<32>(W3, sBias + 1024, sA, stg, acc, tid, lane, wm, wnl);

        // layer 4 diagonal: row r dots W4[:, r]; 4 partials per row
        const int r = tid & 63, p = tid >> 6;   // p in 0..3
        float a4 = 0.0f;
        const __half2* hrow = (const __half2*)(sA + r * LDA + p * 128);
        const float* wcol = W4 + (size_t)(p * 128) * 64 + r;
#pragma unroll 8
        for (int i = 0; i < 64; ++i) {
            const float2 hv = __half22float2(hrow[i]);
            a4 += hv.x * __ldg(wcol + (size_t)(2 * i) * 64);
            a4 += hv.y * __ldg(wcol + (size_t)(2 * i + 1) * 64);
        }
        sRed[p * 64 + r] = a4;
        __syncthreads();
        if (tid < 64) {
            const float v = sRed[tid] + sRed[64 + tid] + sRed[128 + tid]
                          + sRed[192 + tid] + __ldg(b4 + tid);
            if (mlp == 0) {
                sS[tid] = v;
            } else {
                const size_t o = (size_t)b * 64 + tid;
                out[o] = (x[o] - v) * __expf(-sS[tid]);
            }
        }
        __syncthreads();   // sRed/sS settled before next mlp reuses them
    }
}

}  // namespace

extern "C" void kernel_launch(void* const* d_in, const int* in_sizes, int n_in,
                              void* d_out, int out_size) {
    (void)in_sizes; (void)n_in; (void)out_size;
    const float* x    = (const float*)d_in[0];
    const float* koop = (const float*)d_in[1];
    const float* sW1 = (const float*)d_in[2];  const float* sb1 = (const float*)d_in[3];
    const float* sW2 = (const float*)d_in[4];  const float* sb2 = (const float*)d_in[5];
    const float* sW3 = (const float*)d_in[6];  const float* sb3 = (const float*)d_in[7];
    const float* sW4 = (const float*)d_in[8];  const float* sb4 = (const float*)d_in[9];
    const float* tW1 = (const float*)d_in[10]; const float* tb1 = (const float*)d_in[11];
    const float* tW2 = (const float*)d_in[12]; const float* tb2 = (const float*)d_in[13];
    const float* tW3 = (const float*)d_in[14]; const float* tb3 = (const float*)d_in[15];
    const float* tW4 = (const float*)d_in[16]; const float* tb4 = (const float*)d_in[17];
    float* out = (float*)d_out;

    prep_kernel<<<(557056 + 255) / 256, 256>>>(sW1, sW2, sW3, tW1, tW2, tW3);

    cudaFuncSetAttribute(decoder_kernel, cudaFuncAttributeMaxDynamicSharedMemorySize,
                         SMEM_BYTES);
    decoder_kernel<<<2048, NTHREADS, SMEM_BYTES>>>(
        x, koop, sb1, sb2, sb3, sW4, sb4,
        tb1, tb2, tb3, tW4, tb4, out);
}

// round 15
// speedup vs baseline: 1.2252x; 1.0394x over previous
#include <cuda_runtime.h>
#include <cuda_fp16.h>
#include <cstdint>

// Decoder: out[b,d] = (x[b,d] - diag_t[b,d]) * exp(-dias_s[b,d])  [s/t MLPs]
// R14 = R13 (M=64/CTA, 256 thr, 2 CTAs/SM, htanh, A/B reg double-buffer)
// with warp tiles reshaped 2wm x 4wn -> 1wm x 8wn (4Mx4N per warp):
// every warp loads DISTINCT B lines (no duplicate B wavefronts through L1TEX).

namespace {

constexpr int Hn = 512;
constexpr int LDA = 520;        // A stride in halves (1040 B)
constexpr int NTHREADS = 256;   // 8 warps, each: 64 rows x 32 cols (per half)

// blob (u32 = f16x2), fragment-major in 16-k chunks: mlp0 L1,L2,L3 then mlp1
__device__ __align__(16) uint32_t g_wblob[557056];
__constant__ int c_blob_off[7] = {0, 16384, 147456, 278528, 294912, 425984, 557056};

// smem byte offsets
constexpr int OFF_STG  = 66560;    // 64 x 264 halves staging (33792 B)
constexpr int OFF_BIAS = 100352;   // 3 x 512 f32 (6144 B)
constexpr int OFF_RED  = 106496;   // 4 x 64 f32 (1024 B)
constexpr int OFF_S    = 107520;   // 64 f32 (256 B)
constexpr int SMEM_BYTES = 107776; // 105.25 KB -> 2 CTAs/SM

__device__ __forceinline__ void mma16(float c[4], const unsigned a[4],
                                      unsigned b0, unsigned b1) {
    asm volatile(
        "mma.sync.aligned.m16n8k16.row.col.f32.f16.f16.f32 "
        "{%0,%1,%2,%3}, {%4,%5,%6,%7}, {%8,%9}, {%0,%1,%2,%3};"
        : "+f"(c[0]), "+f"(c[1]), "+f"(c[2]), "+f"(c[3])
        : "r"(a[0]), "r"(a[1]), "r"(a[2]), "r"(a[3]), "r"(b0), "r"(b1));
}
__device__ __forceinline__ void ldsm4(unsigned r[4], uint32_t addr) {
    asm volatile("ldmatrix.sync.aligned.m8n8.x4.shared.b16 {%0,%1,%2,%3}, [%4];"
                 : "=r"(r[0]), "=r"(r[1]), "=r"(r[2]), "=r"(r[3]) : "r"(addr));
}
__device__ __forceinline__ void ldg128(uint4& v, const uint4* p) {
    asm volatile("ld.global.nc.v4.u32 {%0,%1,%2,%3}, [%4];"
                 : "=r"(v.x), "=r"(v.y), "=r"(v.z), "=r"(v.w) : "l"(p));
}
// hardware tanh approximation (sm_75+), max abs err ~5e-4
__device__ __forceinline__ float htanh(float x) {
    float y;
    asm("tanh.approx.f32 %0, %1;" : "=f"(y) : "f"(x));
    return y;
}
__device__ __forceinline__ uint32_t pack_f16x2(float lo, float hi) {
    uint32_t r;
    asm("cvt.rn.f16x2.f32 %0, %1, %2;" : "=r"(r) : "f"(hi), "f"(lo));
    return r;
}

// ---- fused prep: all 6 hidden-layer weights -> fp16 fragment blob ----
__global__ void prep_kernel(const float* __restrict__ W0, const float* __restrict__ W1,
                            const float* __restrict__ W2, const float* __restrict__ W3,
                            const float* __restrict__ W4, const float* __restrict__ W5) {
    const int eg = blockIdx.x * blockDim.x + threadIdx.x;
    if (eg >= 557056) return;
    const float* srcs[6] = {W0, W1, W2, W3, W4, W5};
    int slot = 0;
    while (eg >= c_blob_off[slot + 1]) ++slot;
    const float* W = srcs[slot];
    const int e = eg - c_blob_off[slot];
    const int q = e & 3;
    const int lane = (e >> 2) & 31;
    const int p = (e >> 7) & 3;
    const int wn = (e >> 9) & 7;
    const int chunk = e >> 12;
    const int k = chunk * 16 + 2 * (lane & 3) + 8 * (q & 1);
    const int col = wn * 64 + (2 * p + (q >> 1)) * 8 + (lane >> 2);
    float v0 = W[k * Hn + col], v1 = W[(k + 1) * Hn + col];
    uint32_t r;
    asm("cvt.rn.f16x2.f32 %0, %1, %2;" : "=r"(r) : "f"(v1), "f"(v0));
    g_wblob[eg] = r;
}

// ---- main ----
__device__ __forceinline__ void load_a4(unsigned a[4][4], uint32_t ab) {
    ldsm4(a[0], ab);
    ldsm4(a[1], ab + 16 * LDA * 2);
    ldsm4(a[2], ab + 32 * LDA * 2);
    ldsm4(a[3], ab + 48 * LDA * 2);
}

// one 256-col half of a layer; KH = K/16 kh-steps; warp covers 32 cols, 64 rows
template <int KH>
__device__ __forceinline__ void gemm_half(const uint4* __restrict__ Wg, int h,
                                          const __half* sA, float acc[4][4][4],
                                          int lane, int wn) {
#pragma unroll
    for (int mt = 0; mt < 4; ++mt)
#pragma unroll
        for (int nt = 0; nt < 4; ++nt)
#pragma unroll
            for (int q = 0; q < 4; ++q) acc[mt][nt][q] = 0.0f;

    // warp cols: h*256 + wn*32 -> blob block h*4+(wn>>1), p-blocks (wn&1)*2 +{0,1}
    const uint4* bp = Wg + (h * 4 + (wn >> 1)) * 128 + (wn & 1) * 64 + lane;
    const int arow = lane & 15;
    const int acol = (lane >> 4) * 8;
    const uint32_t ab = (unsigned)__cvta_generic_to_shared(sA + arow * LDA + acol);

    unsigned a[2][4][4];
    uint4 b[2][2];
    load_a4(a[0], ab);
    ldg128(b[0][0], bp);
    ldg128(b[0][1], bp + 32);
    ldg128(b[1][0], bp + 1024);
    ldg128(b[1][1], bp + 1056);

#pragma unroll 2
    for (int kh = 0; kh < KH; ++kh) {
        const int s = kh & 1;
        if (kh + 1 < KH) load_a4(a[s ^ 1], ab + (kh + 1) * 32);
#pragma unroll
        for (int mt = 0; mt < 4; ++mt) {
            mma16(acc[mt][0], a[s][mt], b[s][0].x, b[s][0].y);
            mma16(acc[mt][1], a[s][mt], b[s][0].z, b[s][0].w);
        }
        if (kh + 2 < KH) ldg128(b[s][0], bp + (size_t)(kh + 2) * 1024);
#pragma unroll
        for (int mt = 0; mt < 4; ++mt) {
            mma16(acc[mt][2], a[s][mt], b[s][1].x, b[s][1].y);
            mma16(acc[mt][3], a[s][mt], b[s][1].z, b[s][1].w);
        }
        if (kh + 2 < KH) ldg128(b[s][1], bp + (size_t)(kh + 2) * 1024 + 32);
    }
}

// tanh(acc+bias) half 0 -> staging (stride 264 halves), cols 0..255
__device__ __forceinline__ void store_stg(const float acc[4][4][4], char* stg,
                                          const float* lb, int lane, int wn) {
    const int g8 = lane >> 2, t4 = lane & 3;
#pragma unroll
    for (int mt = 0; mt < 4; ++mt) {
        const int row0 = mt * 16 + g8;
#pragma unroll
        for (int nt = 0; nt < 4; ++nt) {
            const int col = wn * 32 + nt * 8 + 2 * t4;
            const float b0 = lb[col], b1 = lb[col + 1];
            *(uint32_t*)(stg + (row0 * 264 + col) * 2) =
                pack_f16x2(htanh(acc[mt][nt][0] + b0), htanh(acc[mt][nt][1] + b1));
            *(uint32_t*)(stg + ((row0 + 8) * 264 + col) * 2) =
                pack_f16x2(htanh(acc[mt][nt][2] + b0), htanh(acc[mt][nt][3] + b1));
        }
    }
}
// tanh(acc+bias) half 1 -> sA cols 256..511
__device__ __forceinline__ void store_hi(const float acc[4][4][4], __half* sA,
                                         const float* lb, int lane, int wn) {
    const int g8 = lane >> 2, t4 = lane & 3;
#pragma unroll
    for (int mt = 0; mt < 4; ++mt) {
        const int row0 = mt * 16 + g8;
#pragma unroll
        for (int nt = 0; nt < 4; ++nt) {
            const int col = 256 + wn * 32 + nt * 8 + 2 * t4;
            const float b0 = lb[col], b1 = lb[col + 1];
            *(uint32_t*)(sA + row0 * LDA + col) =
                pack_f16x2(htanh(acc[mt][nt][0] + b0), htanh(acc[mt][nt][1] + b1));
            *(uint32_t*)(sA + (row0 + 8) * LDA + col) =
                pack_f16x2(htanh(acc[mt][nt][2] + b0), htanh(acc[mt][nt][3] + b1));
        }
    }
}

template <int KH>
__device__ __forceinline__ void process_layer(const uint4* __restrict__ Wg,
                                              const float* lb, __half* sA, char* stg,
                                              float acc[4][4][4], int tid, int lane,
                                              int wn) {
    gemm_half<KH>(Wg, 0, sA, acc, lane, wn);
    store_stg(acc, stg, lb, lane, wn);
    gemm_half<KH>(Wg, 1, sA, acc, lane, wn);
    __syncthreads();   // all A reads done; stg writes visible
    store_hi(acc, sA, lb, lane, wn);
#pragma unroll
    for (int j = 0; j < 8; ++j) {   // copy stg -> sA cols 0..255 (64 rows x 512B)
        const int f4 = tid + j * 256;
        const int row = f4 >> 5, c = f4 & 31;
        *(uint4*)((char*)sA + row * 1040 + c * 16) =
            *(const uint4*)(stg + row * 528 + c * 16);
    }
    __syncthreads();   // sA ready for next layer
}

__global__ __launch_bounds__(NTHREADS, 2)
void decoder_kernel(const float* __restrict__ x, const float* __restrict__ koop,
                    const float* __restrict__ sb1, const float* __restrict__ sb2,
                    const float* __restrict__ sb3,
                    const float* __restrict__ sW4, const float* __restrict__ sb4,
                    const float* __restrict__ tb1, const float* __restrict__ tb2,
                    const float* __restrict__ tb3,
                    const float* __restrict__ tW4, const float* __restrict__ tb4,
                    float* __restrict__ out) {
    extern __shared__ char smem[];
    __half* sA = (__half*)smem;
    char* stg = smem + OFF_STG;
    float* sBias = (float*)(smem + OFF_BIAS);
    float* sRed = (float*)(smem + OFF_RED);
    float* sS = (float*)(smem + OFF_S);

    const int tid = threadIdx.x, lane = tid & 31;
    const int wn = tid >> 5;    // warp id 0..7 = n-tile owner
    const int b = blockIdx.x;

    float acc[4][4][4];

#pragma unroll 1
    for (int mlp = 0; mlp < 2; ++mlp) {
        const uint4* W1 = (const uint4*)(g_wblob + c_blob_off[mlp * 3 + 0]);
        const uint4* W2 = (const uint4*)(g_wblob + c_blob_off[mlp * 3 + 1]);
        const uint4* W3 = (const uint4*)(g_wblob + c_blob_off[mlp * 3 + 2]);
        const float* bias1 = mlp ? tb1 : sb1;
        const float* bias2 = mlp ? tb2 : sb2;
        const float* bias3 = mlp ? tb3 : sb3;
        const float* W4 = mlp ? tW4 : sW4;
        const float* b4 = mlp ? tb4 : sb4;

        // z load: sA[d][l] = koopman[b, l, d] as f16
        const float* kb = koop + (size_t)b * 4096;
        for (int i = tid; i < 4096; i += NTHREADS) {
            const int l = i >> 6, d = i & 63;
            sA[d * LDA + l] = __float2half_rn(kb[i]);
        }
        for (int i = tid; i < 512; i += NTHREADS) {
            sBias[i]        = __ldg(bias1 + i);
            sBias[512 + i]  = __ldg(bias2 + i);
            sBias[1024 + i] = __ldg(bias3 + i);
        }
        __syncthreads();

        process_layer<4>(W1, sBias, sA, stg, acc, tid, lane, wn);
        process_layer<32>(W2, sBias + 512, sA, stg, acc, tid, lane, wn);
        process_layer<32>(W3, sBias + 1024, sA, stg, acc, tid, lane, wn);

        // layer 4 diagonal: row r dots W4[:, r]; 4 partials per row
        const int r = tid & 63, p = tid >> 6;   // p in 0..3
        float a4 = 0.0f;
        const __half2* hrow = (const __half2*)(sA + r * LDA + p * 128);
        const float* wcol = W4 + (size_t)(p * 128) * 64 + r;
#pragma unroll 8
        for (int i = 0; i < 64; ++i) {
            const float2 hv = __half22float2(hrow[i]);
            a4 += hv.x * __ldg(wcol + (size_t)(2 * i) * 64);
            a4 += hv.y * __ldg(wcol + (size_t)(2 * i + 1) * 64);
        }
        sRed[p * 64 + r] = a4;
        __syncthreads();
        if (tid < 64) {
            const float v = sRed[tid] + sRed[64 + tid] + sRed[128 + tid]
                          + sRed[192 + tid] + __ldg(b4 + tid);
            if (mlp == 0) {
                sS[tid] = v;
            } else {
                const size_t o = (size_t)b * 64 + tid;
                out[o] = (x[o] - v) * __expf(-sS[tid]);
            }
        }
        __syncthreads();   // sRed/sS settled before next mlp reuses them
    }
}

}  // namespace

extern "C" void kernel_launch(void* const* d_in, const int* in_sizes, int n_in,
                              void* d_out, int out_size) {
    (void)in_sizes; (void)n_in; (void)out_size;
    const float* x    = (const float*)d_in[0];
    const float* koop = (const float*)d_in[1];
    const float* sW1 = (const float*)d_in[2];  const float* sb1 = (const float*)d_in[3];
    const float* sW2 = (const float*)d_in[4];  const float* sb2 = (const float*)d_in[5];
    const float* sW3 = (const float*)d_in[6];  const float* sb3 = (const float*)d_in[7];
    const float* sW4 = (const float*)d_in[8];  const float* sb4 = (const float*)d_in[9];
    const float* tW1 = (const float*)d_in[10]; const float* tb1 = (const float*)d_in[11];
    const float* tW2 = (const float*)d_in[12]; const float* tb2 = (const float*)d_in[13];
    const float* tW3 = (const float*)d_in[14]; const float* tb3 = (const float*)d_in[15];
    const float* tW4 = (const float*)d_in[16]; const float* tb4 = (const float*)d_in[17];
    float* out = (float*)d_out;

    prep_kernel<<<(557056 + 255) / 256, 256>>>(sW1, sW2, sW3, tW1, tW2, tW3);

    cudaFuncSetAttribute(decoder_kernel, cudaFuncAttributeMaxDynamicSharedMemorySize,
                         SMEM_BYTES);
    decoder_kernel<<<2048, NTHREADS, SMEM_BYTES>>>(
        x, koop, sb1, sb2, sb3, sW4, sb4,
        tb1, tb2, tb3, tW4, tb4, out);
}

// round 16
// speedup vs baseline: 1.2747x; 1.0404x over previous
#include <cuda_runtime.h>
#include <cuda_fp16.h>
#include <cstdint>

// Decoder: out[b,d] = (x[b,d] - diag_t[b,d]) * exp(-diag_s[b,d])
// R15 = R14 (M=64/CTA, 256 thr, 2 CTAs/SM, 1wm x 8wn tiles, htanh,
// A/B register double-buffer, B via distinct LDG.128 from fragment blob)
// with the contiguous A-tile + staging copy replaced by THREE rotating
// 64x256 half-buffers: layers write outputs directly into free buffers,
// zero copies, fewer barriers.

namespace {

constexpr int Hn = 512;
constexpr int LDH = 264;        // half-buffer stride in halves (528 B)
constexpr int NTHREADS = 256;   // 8 warps, each: 64 rows x 32 cols (per half)

// blob (u32 = f16x2), fragment-major in 16-k chunks: mlp0 L1,L2,L3 then mlp1
__device__ __align__(16) uint32_t g_wblob[557056];
__constant__ int c_blob_off[7] = {0, 16384, 147456, 278528, 294912, 425984, 557056};

// smem byte offsets: three half-buffers + bias + reductions
constexpr int OFF_H0   = 0;        // 33792 B each (64 x 264 halves)
constexpr int OFF_H1   = 33792;
constexpr int OFF_H2   = 67584;
constexpr int OFF_BIAS = 101376;   // 3 x 512 f32 (6144 B)
constexpr int OFF_RED  = 107520;   // 4 x 64 f32 (1024 B)
constexpr int OFF_S    = 108544;   // 64 f32 (256 B)
constexpr int SMEM_BYTES = 108800; // 106.25 KB -> 2 CTAs/SM

__device__ __forceinline__ void mma16(float c[4], const unsigned a[4],
                                      unsigned b0, unsigned b1) {
    asm volatile(
        "mma.sync.aligned.m16n8k16.row.col.f32.f16.f16.f32 "
        "{%0,%1,%2,%3}, {%4,%5,%6,%7}, {%8,%9}, {%0,%1,%2,%3};"
        : "+f"(c[0]), "+f"(c[1]), "+f"(c[2]), "+f"(c[3])
        : "r"(a[0]), "r"(a[1]), "r"(a[2]), "r"(a[3]), "r"(b0), "r"(b1));
}
__device__ __forceinline__ void ldsm4(unsigned r[4], uint32_t addr) {
    asm volatile("ldmatrix.sync.aligned.m8n8.x4.shared.b16 {%0,%1,%2,%3}, [%4];"
                 : "=r"(r[0]), "=r"(r[1]), "=r"(r[2]), "=r"(r[3]) : "r"(addr));
}
__device__ __forceinline__ void ldg128(uint4& v, const uint4* p) {
    asm volatile("ld.global.nc.v4.u32 {%0,%1,%2,%3}, [%4];"
                 : "=r"(v.x), "=r"(v.y), "=r"(v.z), "=r"(v.w) : "l"(p));
}
// hardware tanh approximation (sm_75+), max abs err ~5e-4
__device__ __forceinline__ float htanh(float x) {
    float y;
    asm("tanh.approx.f32 %0, %1;" : "=f"(y) : "f"(x));
    return y;
}
__device__ __forceinline__ uint32_t pack_f16x2(float lo, float hi) {
    uint32_t r;
    asm("cvt.rn.f16x2.f32 %0, %1, %2;" : "=r"(r) : "f"(hi), "f"(lo));
    return r;
}

// ---- fused prep: all 6 hidden-layer weights -> fp16 fragment blob ----
__global__ void prep_kernel(const float* __restrict__ W0, const float* __restrict__ W1,
                            const float* __restrict__ W2, const float* __restrict__ W3,
                            const float* __restrict__ W4, const float* __restrict__ W5) {
    const int eg = blockIdx.x * blockDim.x + threadIdx.x;
    if (eg >= 557056) return;
    const float* srcs[6] = {W0, W1, W2, W3, W4, W5};
    int slot = 0;
    while (eg >= c_blob_off[slot + 1]) ++slot;
    const float* W = srcs[slot];
    const int e = eg - c_blob_off[slot];
    const int q = e & 3;
    const int lane = (e >> 2) & 31;
    const int p = (e >> 7) & 3;
    const int wn = (e >> 9) & 7;
    const int chunk = e >> 12;
    const int k = chunk * 16 + 2 * (lane & 3) + 8 * (q & 1);
    const int col = wn * 64 + (2 * p + (q >> 1)) * 8 + (lane >> 2);
    float v0 = W[k * Hn + col], v1 = W[(k + 1) * Hn + col];
    uint32_t r;
    asm("cvt.rn.f16x2.f32 %0, %1, %2;" : "=r"(r) : "f"(v1), "f"(v0));
    g_wblob[eg] = r;
}

// ---- main ----
__device__ __forceinline__ void load_a4(unsigned a[4][4], uint32_t ab) {
    ldsm4(a[0], ab);
    ldsm4(a[1], ab + 16 * LDH * 2);
    ldsm4(a[2], ab + 32 * LDH * 2);
    ldsm4(a[3], ab + 48 * LDH * 2);
}

// one 256-col output half; A spans lo (kh<16) then hi (kh>=16) half-buffers
template <int KH>
__device__ __forceinline__ void gemm_half(const uint4* __restrict__ Wg, int h,
                                          const __half* lo, const __half* hi,
                                          float acc[4][4][4], int lane, int wn) {
#pragma unroll
    for (int mt = 0; mt < 4; ++mt)
#pragma unroll
        for (int nt = 0; nt < 4; ++nt)
#pragma unroll
            for (int q = 0; q < 4; ++q) acc[mt][nt][q] = 0.0f;

    const uint4* bp = Wg + (h * 4 + (wn >> 1)) * 128 + (wn & 1) * 64 + lane;
    const int arow = lane & 15;
    const int acol = (lane >> 4) * 8;
    const uint32_t ab_lo = (unsigned)__cvta_generic_to_shared(lo + arow * LDH + acol);
    const uint32_t ab_hi = (unsigned)__cvta_generic_to_shared(hi + arow * LDH + acol);

    auto aaddr = [&](int kh) -> uint32_t {
        return kh < 16 ? ab_lo + kh * 32 : ab_hi + (kh - 16) * 32;
    };

    unsigned a[2][4][4];
    uint4 b[2][2];
    load_a4(a[0], aaddr(0));
    ldg128(b[0][0], bp);
    ldg128(b[0][1], bp + 32);
    ldg128(b[1][0], bp + 1024);
    ldg128(b[1][1], bp + 1056);

#pragma unroll 2
    for (int kh = 0; kh < KH; ++kh) {
        const int s = kh & 1;
        if (kh + 1 < KH) load_a4(a[s ^ 1], aaddr(kh + 1));
#pragma unroll
        for (int mt = 0; mt < 4; ++mt) {
            mma16(acc[mt][0], a[s][mt], b[s][0].x, b[s][0].y);
            mma16(acc[mt][1], a[s][mt], b[s][0].z, b[s][0].w);
        }
        if (kh + 2 < KH) ldg128(b[s][0], bp + (size_t)(kh + 2) * 1024);
#pragma unroll
        for (int mt = 0; mt < 4; ++mt) {
            mma16(acc[mt][2], a[s][mt], b[s][1].x, b[s][1].y);
            mma16(acc[mt][3], a[s][mt], b[s][1].z, b[s][1].w);
        }
        if (kh + 2 < KH) ldg128(b[s][1], bp + (size_t)(kh + 2) * 1024 + 32);
    }
}

// tanh(acc+bias) -> half-buffer dst at local cols 0..255
__device__ __forceinline__ void store_half(const float acc[4][4][4], __half* dst,
                                           const float* lb, int lane, int wn) {
    const int g8 = lane >> 2, t4 = lane & 3;
#pragma unroll
    for (int mt = 0; mt < 4; ++mt) {
        const int row0 = mt * 16 + g8;
#pragma unroll
        for (int nt = 0; nt < 4; ++nt) {
            const int col = wn * 32 + nt * 8 + 2 * t4;
            const float b0 = lb[col], b1 = lb[col + 1];
            *(uint32_t*)(dst + row0 * LDH + col) =
                pack_f16x2(htanh(acc[mt][nt][0] + b0), htanh(acc[mt][nt][1] + b1));
            *(uint32_t*)(dst + (row0 + 8) * LDH + col) =
                pack_f16x2(htanh(acc[mt][nt][2] + b0), htanh(acc[mt][nt][3] + b1));
        }
    }
}

__global__ __launch_bounds__(NTHREADS, 2)
void decoder_kernel(const float* __restrict__ x, const float* __restrict__ koop,
                    const float* __restrict__ sb1, const float* __restrict__ sb2,
                    const float* __restrict__ sb3,
                    const float* __restrict__ sW4, const float* __restrict__ sb4,
                    const float* __restrict__ tb1, const float* __restrict__ tb2,
                    const float* __restrict__ tb3,
                    const float* __restrict__ tW4, const float* __restrict__ tb4,
                    float* __restrict__ out) {
    extern __shared__ char smem[];
    __half* H0 = (__half*)(smem + OFF_H0);
    __half* H1 = (__half*)(smem + OFF_H1);
    __half* H2 = (__half*)(smem + OFF_H2);
    float* sBias = (float*)(smem + OFF_BIAS);
    float* sRed = (float*)(smem + OFF_RED);
    float* sS = (float*)(smem + OFF_S);

    const int tid = threadIdx.x, lane = tid & 31;
    const int wn = tid >> 5;    // warp id 0..7 = n-tile owner
    const int b = blockIdx.x;

    float acc[4][4][4];

#pragma unroll 1
    for (int mlp = 0; mlp < 2; ++mlp) {
        const uint4* W1 = (const uint4*)(g_wblob + c_blob_off[mlp * 3 + 0]);
        const uint4* W2 = (const uint4*)(g_wblob + c_blob_off[mlp * 3 + 1]);
        const uint4* W3 = (const uint4*)(g_wblob + c_blob_off[mlp * 3 + 2]);
        const float* bias1 = mlp ? tb1 : sb1;
        const float* bias2 = mlp ? tb2 : sb2;
        const float* bias3 = mlp ? tb3 : sb3;
        const float* W4 = mlp ? tW4 : sW4;
        const float* b4 = mlp ? tb4 : sb4;

        // z load into H0: H0[d][l] = koopman[b, l, d] as f16 (cols 0..63)
        const float* kb = koop + (size_t)b * 4096;
        for (int i = tid; i < 4096; i += NTHREADS) {
            const int l = i >> 6, d = i & 63;
            H0[d * LDH + l] = __float2half_rn(kb[i]);
        }
        for (int i = tid; i < 512; i += NTHREADS) {
            sBias[i]        = __ldg(bias1 + i);
            sBias[512 + i]  = __ldg(bias2 + i);
            sBias[1024 + i] = __ldg(bias3 + i);
        }
        __syncthreads();

        // L1 (K=64, all in H0): outputs -> H1 (lo), H2 (hi); both targets free
        gemm_half<4>(W1, 0, H0, H0, acc, lane, wn);
        store_half(acc, H1, sBias, lane, wn);
        gemm_half<4>(W1, 1, H0, H0, acc, lane, wn);
        store_half(acc, H2, sBias + 256, lane, wn);
        __syncthreads();

        // L2: reads (H1, H2); outputs -> H0 (free), then H1 (freed by barrier)
        gemm_half<32>(W2, 0, H1, H2, acc, lane, wn);
        store_half(acc, H0, sBias + 512, lane, wn);
        gemm_half<32>(W2, 1, H1, H2, acc, lane, wn);
        __syncthreads();
        store_half(acc, H1, sBias + 768, lane, wn);
        __syncthreads();

        // L3: reads (H0, H1); outputs -> H2 (freed), then H0 (freed by barrier)
        gemm_half<32>(W3, 0, H0, H1, acc, lane, wn);
        store_half(acc, H2, sBias + 1024, lane, wn);
        gemm_half<32>(W3, 1, H0, H1, acc, lane, wn);
        __syncthreads();
        store_half(acc, H0, sBias + 1280, lane, wn);
        __syncthreads();

        // layer 4 diagonal: h3 lo in H2, hi in H0. Row r dots W4[:, r].
        const int r = tid & 63, p = tid >> 6;   // p in 0..3
        float a4 = 0.0f;
        const __half* hb = (p < 2) ? H2 : H0;
        const __half2* hrow = (const __half2*)(hb + r * LDH + (p & 1) * 128);
        const float* wcol = W4 + (size_t)(p * 128) * 64 + r;
#pragma unroll 8
        for (int i = 0; i < 64; ++i) {
            const float2 hv = __half22float2(hrow[i]);
            a4 += hv.x * __ldg(wcol + (size_t)(2 * i) * 64);
            a4 += hv.y * __ldg(wcol + (size_t)(2 * i + 1) * 64);
        }
        sRed[p * 64 + r] = a4;
        __syncthreads();
        if (tid < 64) {
            const float v = sRed[tid] + sRed[64 + tid] + sRed[128 + tid]
                          + sRed[192 + tid] + __ldg(b4 + tid);
            if (mlp == 0) {
                sS[tid] = v;
            } else {
                const size_t o = (size_t)b * 64 + tid;
                out[o] = (x[o] - v) * __expf(-sS[tid]);
            }
        }
        __syncthreads();   // H0/H2 reads + sS settled before next mlp reuses
    }
}

}  // namespace

extern "C" void kernel_launch(void* const* d_in, const int* in_sizes, int n_in,
                              void* d_out, int out_size) {
    (void)in_sizes; (void)n_in; (void)out_size;
    const float* x    = (const float*)d_in[0];
    const float* koop = (const float*)d_in[1];
    const float* sW1 = (const float*)d_in[2];  const float* sb1 = (const float*)d_in[3];
    const float* sW2 = (const float*)d_in[4];  const float* sb2 = (const float*)d_in[5];
    const float* sW3 = (const float*)d_in[6];  const float* sb3 = (const float*)d_in[7];
    const float* sW4 = (const float*)d_in[8];  const float* sb4 = (const float*)d_in[9];
    const float* tW1 = (const float*)d_in[10]; const float* tb1 = (const float*)d_in[11];
    const float* tW2 = (const float*)d_in[12]; const float* tb2 = (const float*)d_in[13];
    const float* tW3 = (const float*)d_in[14]; const float* tb3 = (const float*)d_in[15];
    const float* tW4 = (const float*)d_in[16]; const float* tb4 = (const float*)d_in[17];
    float* out = (float*)d_out;

    prep_kernel<<<(557056 + 255) / 256, 256>>>(sW1, sW2, sW3, tW1, tW2, tW3);

    cudaFuncSetAttribute(decoder_kernel, cudaFuncAttributeMaxDynamicSharedMemorySize,
                         SMEM_BYTES);
    decoder_kernel<<<2048, NTHREADS, SMEM_BYTES>>>(
        x, koop, sb1, sb2, sb3, sW4, sb4,
        tb1, tb2, tb3, tW4, tb4, out);
}

// round 17
// speedup vs baseline: 1.2773x; 1.0020x over previous
#include <cuda_runtime.h>
#include <cuda_fp16.h>
#include <cstdint>

// Decoder: out[b,d] = (x[b,d] - diag_t[b,d]) * exp(-diag_s[b,d])
// R16 = R15 (M=64/CTA, 256 thr, 2 CTAs/SM, 1wm x 8wn tiles, htanh, rotating
// half-buffers, B via distinct LDG.128 from fragment blob) with the register
// budget rebalanced: A fragments single-buffered, B quad-buffered (lookahead
// 4 kh-steps >> L2 latency), freeing the 128-reg ceiling from spills.

namespace {

constexpr int Hn = 512;
constexpr int LDH = 264;        // half-buffer stride in halves (528 B)
constexpr int NTHREADS = 256;   // 8 warps, each: 64 rows x 32 cols (per half)

// blob (u32 = f16x2), fragment-major in 16-k chunks: mlp0 L1,L2,L3 then mlp1
__device__ __align__(16) uint32_t g_wblob[557056];
__constant__ int c_blob_off[7] = {0, 16384, 147456, 278528, 294912, 425984, 557056};

// smem byte offsets: three half-buffers + bias + reductions
constexpr int OFF_H0   = 0;        // 33792 B each (64 x 264 halves)
constexpr int OFF_H1   = 33792;
constexpr int OFF_H2   = 67584;
constexpr int OFF_BIAS = 101376;   // 3 x 512 f32 (6144 B)
constexpr int OFF_RED  = 107520;   // 4 x 64 f32 (1024 B)
constexpr int OFF_S    = 108544;   // 64 f32 (256 B)
constexpr int SMEM_BYTES = 108800; // 106.25 KB -> 2 CTAs/SM

__device__ __forceinline__ void mma16(float c[4], const unsigned a[4],
                                      unsigned b0, unsigned b1) {
    asm volatile(
        "mma.sync.aligned.m16n8k16.row.col.f32.f16.f16.f32 "
        "{%0,%1,%2,%3}, {%4,%5,%6,%7}, {%8,%9}, {%0,%1,%2,%3};"
        : "+f"(c[0]), "+f"(c[1]), "+f"(c[2]), "+f"(c[3])
        : "r"(a[0]), "r"(a[1]), "r"(a[2]), "r"(a[3]), "r"(b0), "r"(b1));
}
__device__ __forceinline__ void ldsm4(unsigned r[4], uint32_t addr) {
    asm volatile("ldmatrix.sync.aligned.m8n8.x4.shared.b16 {%0,%1,%2,%3}, [%4];"
                 : "=r"(r[0]), "=r"(r[1]), "=r"(r[2]), "=r"(r[3]) : "r"(addr));
}
__device__ __forceinline__ void ldg128(uint4& v, const uint4* p) {
    asm volatile("ld.global.nc.v4.u32 {%0,%1,%2,%3}, [%4];"
                 : "=r"(v.x), "=r"(v.y), "=r"(v.z), "=r"(v.w) : "l"(p));
}
// hardware tanh approximation (sm_75+), max abs err ~5e-4
__device__ __forceinline__ float htanh(float x) {
    float y;
    asm("tanh.approx.f32 %0, %1;" : "=f"(y) : "f"(x));
    return y;
}
__device__ __forceinline__ uint32_t pack_f16x2(float lo, float hi) {
    uint32_t r;
    asm("cvt.rn.f16x2.f32 %0, %1, %2;" : "=r"(r) : "f"(hi), "f"(lo));
    return r;
}

// ---- fused prep: all 6 hidden-layer weights -> fp16 fragment blob ----
__global__ void prep_kernel(const float* __restrict__ W0, const float* __restrict__ W1,
                            const float* __restrict__ W2, const float* __restrict__ W3,
                            const float* __restrict__ W4, const float* __restrict__ W5) {
    const int eg = blockIdx.x * blockDim.x + threadIdx.x;
    if (eg >= 557056) return;
    const float* srcs[6] = {W0, W1, W2, W3, W4, W5};
    int slot = 0;
    while (eg >= c_blob_off[slot + 1]) ++slot;
    const float* W = srcs[slot];
    const int e = eg - c_blob_off[slot];
    const int q = e & 3;
    const int lane = (e >> 2) & 31;
    const int p = (e >> 7) & 3;
    const int wn = (e >> 9) & 7;
    const int chunk = e >> 12;
    const int k = chunk * 16 + 2 * (lane & 3) + 8 * (q & 1);
    const int col = wn * 64 + (2 * p + (q >> 1)) * 8 + (lane >> 2);
    float v0 = W[k * Hn + col], v1 = W[(k + 1) * Hn + col];
    uint32_t r;
    asm("cvt.rn.f16x2.f32 %0, %1, %2;" : "=r"(r) : "f"(v1), "f"(v0));
    g_wblob[eg] = r;
}

// ---- main ----
__device__ __forceinline__ void load_a4(unsigned a[4][4], uint32_t ab) {
    ldsm4(a[0], ab);
    ldsm4(a[1], ab + 16 * LDH * 2);
    ldsm4(a[2], ab + 32 * LDH * 2);
    ldsm4(a[3], ab + 48 * LDH * 2);
}

// one 256-col output half; A spans lo (kh<16) then hi (kh>=16) half-buffers.
// B quad-buffered with static kh&3 indexing (KH divisible by 4).
template <int KH>
__device__ __forceinline__ void gemm_half(const uint4* __restrict__ Wg, int h,
                                          const __half* lo, const __half* hi,
                                          float acc[4][4][4], int lane, int wn) {
    static_assert(KH % 4 == 0, "KH must be divisible by 4");
#pragma unroll
    for (int mt = 0; mt < 4; ++mt)
#pragma unroll
        for (int nt = 0; nt < 4; ++nt)
#pragma unroll
            for (int q = 0; q < 4; ++q) acc[mt][nt][q] = 0.0f;

    const uint4* bp = Wg + (h * 4 + (wn >> 1)) * 128 + (wn & 1) * 64 + lane;
    const int arow = lane & 15;
    const int acol = (lane >> 4) * 8;
    const uint32_t ab_lo = (unsigned)__cvta_generic_to_shared(lo + arow * LDH + acol);
    const uint32_t ab_hi = (unsigned)__cvta_generic_to_shared(hi + arow * LDH + acol);

    auto aaddr = [&](int kh) -> uint32_t {
        return kh < 16 ? ab_lo + kh * 32 : ab_hi + (kh - 16) * 32;
    };

    uint4 b[4][2];
#pragma unroll
    for (int j = 0; j < 4; ++j) {
        if (j < KH) {
            ldg128(b[j][0], bp + (size_t)j * 1024);
            ldg128(b[j][1], bp + (size_t)j * 1024 + 32);
        }
    }

#pragma unroll 4
    for (int kh = 0; kh < KH; ++kh) {
        const int s = kh & 3;
        unsigned a[4][4];
        load_a4(a, aaddr(kh));
#pragma unroll
        for (int mt = 0; mt < 4; ++mt) {
            mma16(acc[mt][0], a[mt], b[s][0].x, b[s][0].y);
            mma16(acc[mt][1], a[mt], b[s][0].z, b[s][0].w);
        }
        if (kh + 4 < KH) ldg128(b[s][0], bp + (size_t)(kh + 4) * 1024);
#pragma unroll
        for (int mt = 0; mt < 4; ++mt) {
            mma16(acc[mt][2], a[mt], b[s][1].x, b[s][1].y);
            mma16(acc[mt][3], a[mt], b[s][1].z, b[s][1].w);
        }
        if (kh + 4 < KH) ldg128(b[s][1], bp + (size_t)(kh + 4) * 1024 + 32);
    }
}

// tanh(acc+bias) -> half-buffer dst at local cols 0..255
__device__ __forceinline__ void store_half(const float acc[4][4][4], __half* dst,
                                           const float* lb, int lane, int wn) {
    const int g8 = lane >> 2, t4 = lane & 3;
#pragma unroll
    for (int mt = 0; mt < 4; ++mt) {
        const int row0 = mt * 16 + g8;
#pragma unroll
        for (int nt = 0; nt < 4; ++nt) {
            const int col = wn * 32 + nt * 8 + 2 * t4;
            const float b0 = lb[col], b1 = lb[col + 1];
            *(uint32_t*)(dst + row0 * LDH + col) =
                pack_f16x2(htanh(acc[mt][nt][0] + b0), htanh(acc[mt][nt][1] + b1));
            *(uint32_t*)(dst + (row0 + 8) * LDH + col) =
                pack_f16x2(htanh(acc[mt][nt][2] + b0), htanh(acc[mt][nt][3] + b1));
        }
    }
}

__global__ __launch_bounds__(NTHREADS, 2)
void decoder_kernel(const float* __restrict__ x, const float* __restrict__ koop,
                    const float* __restrict__ sb1, const float* __restrict__ sb2,
                    const float* __restrict__ sb3,
                    const float* __restrict__ sW4, const float* __restrict__ sb4,
                    const float* __restrict__ tb1, const float* __restrict__ tb2,
                    const float* __restrict__ tb3,
                    const float* __restrict__ tW4, const float* __restrict__ tb4,
                    float* __restrict__ out) {
    extern __shared__ char smem[];
    __half* H0 = (__half*)(smem + OFF_H0);
    __half* H1 = (__half*)(smem + OFF_H1);
    __half* H2 = (__half*)(smem + OFF_H2);
    float* sBias = (float*)(smem + OFF_BIAS);
    float* sRed = (float*)(smem + OFF_RED);
    float* sS = (float*)(smem + OFF_S);

    const int tid = threadIdx.x, lane = tid & 31;
    const int wn = tid >> 5;    // warp id 0..7 = n-tile owner
    const int b = blockIdx.x;

    float acc[4][4][4];

#pragma unroll 1
    for (int mlp = 0; mlp < 2; ++mlp) {
        const uint4* W1 = (const uint4*)(g_wblob + c_blob_off[mlp * 3 + 0]);
        const uint4* W2 = (const uint4*)(g_wblob + c_blob_off[mlp * 3 + 1]);
        const uint4* W3 = (const uint4*)(g_wblob + c_blob_off[mlp * 3 + 2]);
        const float* bias1 = mlp ? tb1 : sb1;
        const float* bias2 = mlp ? tb2 : sb2;
        const float* bias3 = mlp ? tb3 : sb3;
        const float* W4 = mlp ? tW4 : sW4;
        const float* b4 = mlp ? tb4 : sb4;

        // z load into H0: H0[d][l] = koopman[b, l, d] as f16 (cols 0..63)
        const float* kb = koop + (size_t)b * 4096;
        for (int i = tid; i < 4096; i += NTHREADS) {
            const int l = i >> 6, d = i & 63;
            H0[d * LDH + l] = __float2half_rn(kb[i]);
        }
        for (int i = tid; i < 512; i += NTHREADS) {
            sBias[i]        = __ldg(bias1 + i);
            sBias[512 + i]  = __ldg(bias2 + i);
            sBias[1024 + i] = __ldg(bias3 + i);
        }
        __syncthreads();

        // L1 (K=64, all in H0): outputs -> H1 (lo), H2 (hi); both targets free
        gemm_half<4>(W1, 0, H0, H0, acc, lane, wn);
        store_half(acc, H1, sBias, lane, wn);
        gemm_half<4>(W1, 1, H0, H0, acc, lane, wn);
        store_half(acc, H2, sBias + 256, lane, wn);
        __syncthreads();

        // L2: reads (H1, H2); outputs -> H0 (free), then H1 (freed by barrier)
        gemm_half<32>(W2, 0, H1, H2, acc, lane, wn);
        store_half(acc, H0, sBias + 512, lane, wn);
        gemm_half<32>(W2, 1, H1, H2, acc, lane, wn);
        __syncthreads();
        store_half(acc, H1, sBias + 768, lane, wn);
        __syncthreads();

        // L3: reads (H0, H1); outputs -> H2 (freed), then H0 (freed by barrier)
        gemm_half<32>(W3, 0, H0, H1, acc, lane, wn);
        store_half(acc, H2, sBias + 1024, lane, wn);
        gemm_half<32>(W3, 1, H0, H1, acc, lane, wn);
        __syncthreads();
        store_half(acc, H0, sBias + 1280, lane, wn);
        __syncthreads();

        // layer 4 diagonal: h3 lo in H2, hi in H0. Row r dots W4[:, r].
        const int r = tid & 63, p = tid >> 6;   // p in 0..3
        float a0 = 0.0f, a1 = 0.0f;
        const __half* hb = (p < 2) ? H2 : H0;
        const __half2* hrow = (const __half2*)(hb + r * LDH + (p & 1) * 128);
        const float* wcol = W4 + (size_t)(p * 128) * 64 + r;
#pragma unroll 8
        for (int i = 0; i < 64; i += 2) {
            const float2 hv0 = __half22float2(hrow[i]);
            const float2 hv1 = __half22float2(hrow[i + 1]);
            a0 += hv0.x * __ldg(wcol + (size_t)(2 * i) * 64);
            a1 += hv0.y * __ldg(wcol + (size_t)(2 * i + 1) * 64);
            a0 += hv1.x * __ldg(wcol + (size_t)(2 * i + 2) * 64);
            a1 += hv1.y * __ldg(wcol + (size_t)(2 * i + 3) * 64);
        }
        sRed[p * 64 + r] = a0 + a1;
        __syncthreads();
        if (tid < 64) {
            const float v = sRed[tid] + sRed[64 + tid] + sRed[128 + tid]
                          + sRed[192 + tid] + __ldg(b4 + tid);
            if (mlp == 0) {
                sS[tid] = v;
            } else {
                const size_t o = (size_t)b * 64 + tid;
                out[o] = (x[o] - v) * __expf(-sS[tid]);
            }
        }
        __syncthreads();   // H0/H2 reads + sS settled before next mlp reuses
    }
}

}  // namespace

extern "C" void kernel_launch(void* const* d_in, const int* in_sizes, int n_in,
                              void* d_out, int out_size) {
    (void)in_sizes; (void)n_in; (void)out_size;
    const float* x    = (const float*)d_in[0];
    const float* koop = (const float*)d_in[1];
    const float* sW1 = (const float*)d_in[2];  const float* sb1 = (const float*)d_in[3];
    const float* sW2 = (const float*)d_in[4];  const float* sb2 = (const float*)d_in[5];
    const float* sW3 = (const float*)d_in[6];  const float* sb3 = (const float*)d_in[7];
    const float* sW4 = (const float*)d_in[8];  const float* sb4 = (const float*)d_in[9];
    const float* tW1 = (const float*)d_in[10]; const float* tb1 = (const float*)d_in[11];
    const float* tW2 = (const float*)d_in[12]; const float* tb2 = (const float*)d_in[13];
    const float* tW3 = (const float*)d_in[14]; const float* tb3 = (const float*)d_in[15];
    const float* tW4 = (const float*)d_in[16]; const float* tb4 = (const float*)d_in[17];
    float* out = (float*)d_out;

    prep_kernel<<<(557056 + 255) / 256, 256>>>(sW1, sW2, sW3, tW1, tW2, tW3);

    cudaFuncSetAttribute(decoder_kernel, cudaFuncAttributeMaxDynamicSharedMemorySize,
                         SMEM_BYTES);
    decoder_kernel<<<2048, NTHREADS, SMEM_BYTES>>>(
        x, koop, sb1, sb2, sb3, sW4, sb4,
        tb1, tb2, tb3, tW4, tb4, out);
}